// round 1
// baseline (speedup 1.0000x reference)
#include <cuda_runtime.h>
#include <cuda_bf16.h>

// Problem constants
#define BATCH 2
#define SEQ 2048
#define DMODEL 1024
#define NH 16
#define NKV 4
#define HD 64
// d_out layout: out [B,S,D] | new_k [B,S,KVH,HD] | new_v [B,S,KVH,HD]
#define OUT_ELEMS  (BATCH*SEQ*DMODEL)          // 4194304
#define KV_ELEMS   (BATCH*SEQ*NKV*HD)          // 1048576

// Scratch (device globals; no runtime allocation allowed)
__device__ float g_q [BATCH*SEQ*NH*HD];   // q after RoPE+scale, [B,S,H,HD]
__device__ float g_ao[BATCH*SEQ*NH*HD];   // attention output,    [B,S,H,HD]

// ---------------------------------------------------------------------------
// SGEMM: C[M,N] = A[M,K] @ B[K,N], all row-major fp32.
// 128x128 tile, BK=16, 256 threads, 8x8 per-thread register tile.
// ---------------------------------------------------------------------------
__global__ __launch_bounds__(256) void sgemm128(const float* __restrict__ A,
                                                const float* __restrict__ B,
                                                float* __restrict__ C,
                                                int M, int N, int K) {
    __shared__ float As[16][132];   // transposed: As[k][m]; 132 keeps 16B alignment
    __shared__ float Bs[16][128];   // natural:    Bs[k][n]

    int t = threadIdx.x;
    int m0 = blockIdx.y * 128;
    int n0 = blockIdx.x * 128;
    int trow = t >> 4;      // 0..15 (m direction)
    int tcol = t & 15;      // 0..15 (n direction)

    float acc[8][8];
#pragma unroll
    for (int r = 0; r < 8; r++)
#pragma unroll
        for (int c = 0; c < 8; c++) acc[r][c] = 0.f;

    for (int k0 = 0; k0 < K; k0 += 16) {
#pragma unroll
        for (int i = 0; i < 2; i++) {
            int idx = t + 256 * i;
            // A tile: 128 rows x 16 cols = 512 float4
            int ar = idx >> 2, ac = idx & 3;
            float4 av = *(const float4*)(A + (size_t)(m0 + ar) * K + k0 + ac * 4);
            As[ac*4+0][ar] = av.x;
            As[ac*4+1][ar] = av.y;
            As[ac*4+2][ar] = av.z;
            As[ac*4+3][ar] = av.w;
            // B tile: 16 rows x 128 cols = 512 float4
            int br = idx >> 5, bc = idx & 31;
            float4 bv = *(const float4*)(B + (size_t)(k0 + br) * N + n0 + bc * 4);
            *(float4*)&Bs[br][bc*4] = bv;
        }
        __syncthreads();
#pragma unroll
        for (int kk = 0; kk < 16; kk++) {
            float4 a0 = *(float4*)&As[kk][trow*8];
            float4 a1 = *(float4*)&As[kk][trow*8+4];
            float4 b0 = *(float4*)&Bs[kk][tcol*8];
            float4 b1 = *(float4*)&Bs[kk][tcol*8+4];
            float av[8] = {a0.x,a0.y,a0.z,a0.w,a1.x,a1.y,a1.z,a1.w};
            float bv[8] = {b0.x,b0.y,b0.z,b0.w,b1.x,b1.y,b1.z,b1.w};
#pragma unroll
            for (int r = 0; r < 8; r++)
#pragma unroll
                for (int c = 0; c < 8; c++) acc[r][c] += av[r] * bv[c];
        }
        __syncthreads();
    }

#pragma unroll
    for (int r = 0; r < 8; r++) {
        float4 c0 = make_float4(acc[r][0], acc[r][1], acc[r][2], acc[r][3]);
        float4 c1 = make_float4(acc[r][4], acc[r][5], acc[r][6], acc[r][7]);
        float* Cp = C + (size_t)(m0 + trow*8 + r) * N + n0 + tcol*8;
        *(float4*)(Cp)     = c0;
        *(float4*)(Cp + 4) = c1;
    }
}

// ---------------------------------------------------------------------------
// RoPE in place: q in g_q (heads 0..15, also *0.125 scale), k in d_out kv
// region (heads 16..19 -> kv head 0..3). One thread per (b,s,head,pair j).
// ---------------------------------------------------------------------------
__global__ __launch_bounds__(256) void rope_kernel(float* __restrict__ q,
                                                   float* __restrict__ kout,
                                                   const float* __restrict__ cosT,
                                                   const float* __restrict__ sinT) {
    int idx = blockIdx.x * blockDim.x + threadIdx.x;
    const int total = BATCH * SEQ * (NH + NKV) * (HD/2);
    if (idx >= total) return;
    int j = idx & 31;
    int rest = idx >> 5;
    int head = rest % (NH + NKV);
    int s = (rest / (NH + NKV)) % SEQ;
    int b = rest / ((NH + NKV) * SEQ);

    float c  = cosT[s * 32 + j];
    float sn = sinT[s * 32 + j];

    float* base;
    float scale;
    if (head < NH) {
        base = q + ((((size_t)b * SEQ + s) * NH + head) << 6);
        scale = 0.125f;   // 1/sqrt(HD), exact power of 2
    } else {
        base = kout + ((((size_t)b * SEQ + s) * NKV + (head - NH)) << 6);
        scale = 1.0f;
    }
    float x1 = base[j];
    float x2 = base[j + 32];
    base[j]      = (x1 * c - x2 * sn) * scale;
    base[j + 32] = (x2 * c + x1 * sn) * scale;
}

// ---------------------------------------------------------------------------
// Flash attention, fp32. Block: 64 queries x one head. Key tiles of 64,
// causal tiles skipped. 128 threads. Q/K/P stored transposed in smem so all
// inner-loop reads are LDS.128.
// ---------------------------------------------------------------------------
#define SPAD 68
#define ATTN_SMEM ((3*64*SPAD + 128) * (int)sizeof(float))

__global__ __launch_bounds__(128) void attn_kernel(const float* __restrict__ Q,
                                                   const float* __restrict__ Kg,
                                                   const float* __restrict__ Vg,
                                                   float* __restrict__ O) {
    extern __shared__ float sm[];
    float* qs    = sm;                 // [d][q]  64 x SPAD
    float* kvs   = sm + 64*SPAD;       // K: [d][key], then V: [key][d]
    float* ss    = sm + 2*64*SPAD;     // [key][q] (scores, then P)
    float* alpha = sm + 3*64*SPAD;     // [64]
    float* linv  = alpha + 64;         // [64]

    int t  = threadIdx.x;
    int qt = blockIdx.x;   // query tile (0..31)
    int h  = blockIdx.y;   // head
    int b  = blockIdx.z;   // batch
    int tx = t & 15, ty = t >> 4;
    int i0 = tx * 4;       // query rows owned
    int j0 = ty * 8;       // key cols / hd cols owned

    // Load Q tile transposed (row stride in gmem = NH*HD = 1024)
    const float* Qb = Q + ((((size_t)b * SEQ) + (size_t)qt * 64) * NH + h) * HD;
#pragma unroll
    for (int i = 0; i < 8; i++) {
        int idx = t + 128 * i;          // 1024 float4 total
        int row = idx >> 4, c4 = idx & 15;
        float4 v = *(const float4*)(Qb + (size_t)row * (NH*HD) + c4 * 4);
        qs[(c4*4+0)*SPAD + row] = v.x;
        qs[(c4*4+1)*SPAD + row] = v.y;
        qs[(c4*4+2)*SPAD + row] = v.z;
        qs[(c4*4+3)*SPAD + row] = v.w;
    }

    float m_i = -1e30f, l_i = 0.f;
    float o[4][8];
#pragma unroll
    for (int r = 0; r < 4; r++)
#pragma unroll
        for (int c = 0; c < 8; c++) o[r][c] = 0.f;

    int kvh = h >> 2;   // n_rep = 4
    const float* Kb = Kg + ((size_t)b * SEQ * NKV + kvh) * HD;   // row stride NKV*HD=256
    const float* Vb = Vg + ((size_t)b * SEQ * NKV + kvh) * HD;

    for (int kt = 0; kt <= qt; kt++) {
        __syncthreads();   // prev iter done with kvs (V) and ss
        // Load K tile transposed
        const float* Kt = Kb + (size_t)kt * 64 * (NKV*HD);
#pragma unroll
        for (int i = 0; i < 8; i++) {
            int idx = t + 128 * i;
            int row = idx >> 4, c4 = idx & 15;
            float4 v = *(const float4*)(Kt + (size_t)row * (NKV*HD) + c4 * 4);
            kvs[(c4*4+0)*SPAD + row] = v.x;
            kvs[(c4*4+1)*SPAD + row] = v.y;
            kvs[(c4*4+2)*SPAD + row] = v.z;
            kvs[(c4*4+3)*SPAD + row] = v.w;
        }
        __syncthreads();

        // S = Q K^T (q already carries the 1/8 scale)
        float s[4][8];
#pragma unroll
        for (int r = 0; r < 4; r++)
#pragma unroll
            for (int c = 0; c < 8; c++) s[r][c] = 0.f;
#pragma unroll 8
        for (int kk = 0; kk < 64; kk++) {
            float4 a  = *(float4*)(qs  + kk*SPAD + i0);
            float4 b0 = *(float4*)(kvs + kk*SPAD + j0);
            float4 b1 = *(float4*)(kvs + kk*SPAD + j0 + 4);
            float av[4] = {a.x, a.y, a.z, a.w};
            float bv[8] = {b0.x,b0.y,b0.z,b0.w,b1.x,b1.y,b1.z,b1.w};
#pragma unroll
            for (int r = 0; r < 4; r++)
#pragma unroll
                for (int c = 0; c < 8; c++) s[r][c] += av[r] * bv[c];
        }
        if (kt == qt) {   // diagonal tile: hard causal mask (== -1e9 additive in fp32)
#pragma unroll
            for (int r = 0; r < 4; r++)
#pragma unroll
                for (int c = 0; c < 8; c++)
                    if (j0 + c > i0 + r) s[r][c] = -1e30f;
        }
        __syncthreads();   // all reads of kvs(K) complete

        // Store S transposed [key][q]; load V tile (natural [key][d]) into kvs
#pragma unroll
        for (int c = 0; c < 8; c++) {
            float4 sv = make_float4(s[0][c], s[1][c], s[2][c], s[3][c]);
            *(float4*)(ss + (j0 + c)*SPAD + i0) = sv;
        }
        const float* Vt = Vb + (size_t)kt * 64 * (NKV*HD);
#pragma unroll
        for (int i = 0; i < 8; i++) {
            int idx = t + 128 * i;
            int row = idx >> 4, c4 = idx & 15;
            float4 v = *(const float4*)(Vt + (size_t)row * (NKV*HD) + c4 * 4);
            *(float4*)(kvs + row*SPAD + c4*4) = v;
        }
        __syncthreads();

        // Online softmax: one thread per query row
        if (t < 64) {
            float mx = m_i;
#pragma unroll 8
            for (int kk = 0; kk < 64; kk++) mx = fmaxf(mx, ss[kk*SPAD + t]);
            float al = __expf(m_i - mx);
            float lsum = 0.f;
#pragma unroll 8
            for (int kk = 0; kk < 64; kk++) {
                float p = __expf(ss[kk*SPAD + t] - mx);
                ss[kk*SPAD + t] = p;
                lsum += p;
            }
            l_i = l_i * al + lsum;
            m_i = mx;
            alpha[t] = al;
        }
        __syncthreads();

        // O = O*alpha + P V
        float al4[4];
#pragma unroll
        for (int r = 0; r < 4; r++) al4[r] = alpha[i0 + r];
#pragma unroll
        for (int r = 0; r < 4; r++)
#pragma unroll
            for (int c = 0; c < 8; c++) o[r][c] *= al4[r];
#pragma unroll 8
        for (int kk = 0; kk < 64; kk++) {
            float4 p  = *(float4*)(ss  + kk*SPAD + i0);
            float4 v0 = *(float4*)(kvs + kk*SPAD + j0);
            float4 v1 = *(float4*)(kvs + kk*SPAD + j0 + 4);
            float pv[4] = {p.x, p.y, p.z, p.w};
            float vv[8] = {v0.x,v0.y,v0.z,v0.w,v1.x,v1.y,v1.z,v1.w};
#pragma unroll
            for (int r = 0; r < 4; r++)
#pragma unroll
                for (int c = 0; c < 8; c++) o[r][c] += pv[r] * vv[c];
        }
    }

    if (t < 64) linv[t] = 1.f / l_i;
    __syncthreads();

    float* Ob = O + ((((size_t)b * SEQ) + (size_t)qt * 64) * NH + h) * HD;
#pragma unroll
    for (int r = 0; r < 4; r++) {
        float inv = linv[i0 + r];
        float4 c0 = make_float4(o[r][0]*inv, o[r][1]*inv, o[r][2]*inv, o[r][3]*inv);
        float4 c1 = make_float4(o[r][4]*inv, o[r][5]*inv, o[r][6]*inv, o[r][7]*inv);
        float* Op = Ob + (size_t)(i0 + r) * (NH*HD) + j0;
        *(float4*)(Op)     = c0;
        *(float4*)(Op + 4) = c1;
    }
}

// ---------------------------------------------------------------------------
extern "C" void kernel_launch(void* const* d_in, const int* in_sizes, int n_in,
                              void* d_out, int out_size) {
    const float* x    = (const float*)d_in[0];
    const float* cosT = (const float*)d_in[1];
    const float* sinT = (const float*)d_in[2];
    // d_in[3] = mask: unused (hard causal mask is bit-identical in fp32)
    const float* wq   = (const float*)d_in[4];
    const float* wk   = (const float*)d_in[5];
    const float* wv   = (const float*)d_in[6];
    const float* wo   = (const float*)d_in[7];

    float* out  = (float*)d_out;
    float* kout = out + OUT_ELEMS;
    float* vout = out + OUT_ELEMS + KV_ELEMS;

    float *qbuf = nullptr, *aobuf = nullptr;
    cudaGetSymbolAddress((void**)&qbuf,  g_q);
    cudaGetSymbolAddress((void**)&aobuf, g_ao);

    const int M = BATCH * SEQ;   // 4096

    // QKV projections (k, v written straight into d_out; rope fixes k in place)
    sgemm128<<<dim3(DMODEL/128, M/128), 256>>>(x, wq, qbuf, M, NH*HD,  DMODEL);
    sgemm128<<<dim3((NKV*HD)/128, M/128), 256>>>(x, wk, kout, M, NKV*HD, DMODEL);
    sgemm128<<<dim3((NKV*HD)/128, M/128), 256>>>(x, wv, vout, M, NKV*HD, DMODEL);

    // RoPE (q gets the 0.125 attention scale folded in)
    {
        int total = BATCH * SEQ * (NH + NKV) * (HD/2);
        rope_kernel<<<(total + 255) / 256, 256>>>(qbuf, kout, cosT, sinT);
    }

    // Flash attention
    cudaFuncSetAttribute(attn_kernel, cudaFuncAttributeMaxDynamicSharedMemorySize,
                         ATTN_SMEM);
    attn_kernel<<<dim3(SEQ/64, NH, BATCH), 128, ATTN_SMEM>>>(qbuf, kout, vout, aobuf);

    // Output projection
    sgemm128<<<dim3(DMODEL/128, M/128), 256>>>(aobuf, wo, out, M, DMODEL, DMODEL);
}

// round 3
// speedup vs baseline: 1.2653x; 1.2653x over previous
#include <cuda_runtime.h>
#include <cuda_bf16.h>
#include <cstdint>

// Problem constants
#define BATCH 2
#define SEQ 2048
#define DMODEL 1024
#define NH 16
#define NKV 4
#define HD 64
#define OUT_ELEMS  (BATCH*SEQ*DMODEL)
#define KV_ELEMS   (BATCH*SEQ*NKV*HD)

#define MTOT (BATCH*SEQ)        // 4096
#define GK   (3*DMODEL)         // 3072 split-K (hi|lo|hi vs hi|hi|lo)

// ---------------------------------------------------------------------------
// Scratch (device globals; no runtime allocation allowed)
// ---------------------------------------------------------------------------
__device__ float g_q [MTOT*NH*HD];                 // q after RoPE+scale
__device__ float g_ao[MTOT*NH*HD];                 // attention output
__device__ __nv_bfloat16 g_xc [MTOT*GK];           // x split [M, 3K]
__device__ __nv_bfloat16 g_aoc[MTOT*GK];           // ao split [M, 3K]
__device__ __nv_bfloat16 g_wqt[(NH*HD)*GK];        // wq^T split [N, 3K]
__device__ __nv_bfloat16 g_wkt[(NKV*HD)*GK];
__device__ __nv_bfloat16 g_wvt[(NKV*HD)*GK];
__device__ __nv_bfloat16 g_wot[DMODEL*GK];

// ---------------------------------------------------------------------------
// Baseline-PTX helpers (sm_80-era instructions only: ldmatrix / mma / cp.async)
// ---------------------------------------------------------------------------
__device__ __forceinline__ uint32_t smem_u32(const void* p) {
    uint32_t a;
    asm("{ .reg .u64 t; cvta.to.shared.u64 t, %1; cvt.u32.u64 %0, t; }" : "=r"(a) : "l"(p));
    return a;
}
__device__ __forceinline__ void cp16(uint32_t saddr, const void* g) {
    asm volatile("cp.async.cg.shared.global [%0], [%1], 16;" :: "r"(saddr), "l"(g) : "memory");
}
#define CP_COMMIT() asm volatile("cp.async.commit_group;" ::: "memory")
#define CP_WAIT(n)  asm volatile("cp.async.wait_group %0;" :: "n"(n) : "memory")

__device__ __forceinline__ void ldsm4(uint32_t& r0, uint32_t& r1, uint32_t& r2, uint32_t& r3,
                                      uint32_t a) {
    asm volatile("ldmatrix.sync.aligned.m8n8.x4.shared.b16 {%0,%1,%2,%3}, [%4];"
                 : "=r"(r0), "=r"(r1), "=r"(r2), "=r"(r3) : "r"(a));
}
__device__ __forceinline__ void mma16816(float* c, uint32_t a0, uint32_t a1, uint32_t a2,
                                         uint32_t a3, uint32_t b0, uint32_t b1) {
    asm volatile(
        "mma.sync.aligned.m16n8k16.row.col.f32.bf16.bf16.f32 "
        "{%0,%1,%2,%3},{%4,%5,%6,%7},{%8,%9},{%0,%1,%2,%3};"
        : "+f"(c[0]), "+f"(c[1]), "+f"(c[2]), "+f"(c[3])
        : "r"(a0), "r"(a1), "r"(a2), "r"(a3), "r"(b0), "r"(b1));
}

// ---------------------------------------------------------------------------
// Split conversions: v -> (hi, lo) bf16 with hi = rn(v), lo = rn(v - hi)
// ---------------------------------------------------------------------------
__device__ __forceinline__ void split_bf16(float v, __nv_bfloat16& hi, __nv_bfloat16& lo) {
    hi = __float2bfloat16(v);
    lo = __float2bfloat16(v - __bfloat162float(hi));
}

// A-side: src [M, K] fp32 -> dst [M, 3K] = [hi | lo | hi]
__global__ __launch_bounds__(256) void conv_a(const float* __restrict__ src,
                                              __nv_bfloat16* __restrict__ dst) {
    int idx = blockIdx.x * blockDim.x + threadIdx.x;   // per float4
    const int K = DMODEL;
    if (idx >= MTOT * K / 4) return;
    int flat = idx * 4;
    int m = flat / K, k = flat % K;
    float4 v = *(const float4*)(src + flat);
    float vv[4] = {v.x, v.y, v.z, v.w};
    __nv_bfloat16 h[4], l[4];
#pragma unroll
    for (int j = 0; j < 4; j++) split_bf16(vv[j], h[j], l[j]);
    __nv_bfloat16* row = dst + (size_t)m * GK;
    *(uint2*)(row + k)         = *(uint2*)h;
    *(uint2*)(row + K + k)     = *(uint2*)l;
    *(uint2*)(row + 2 * K + k) = *(uint2*)h;
}

// B-side: src [K, N] fp32 -> dst [N, 3K] = [hi | hi | lo] (transposed)
__global__ void conv_w(const float* __restrict__ src, __nv_bfloat16* __restrict__ dst, int N) {
    __shared__ float tile[32][33];
    const int K = DMODEL;
    int k0 = blockIdx.y * 32, n0 = blockIdx.x * 32;
    int tx = threadIdx.x, ty = threadIdx.y;   // 32 x 8
#pragma unroll
    for (int i = 0; i < 32; i += 8)
        tile[ty + i][tx] = src[(size_t)(k0 + ty + i) * N + n0 + tx];
    __syncthreads();
#pragma unroll
    for (int i = 0; i < 32; i += 8) {
        int n = n0 + ty + i, k = k0 + tx;
        __nv_bfloat16 h, l;
        split_bf16(tile[tx][ty + i], h, l);
        __nv_bfloat16* row = dst + (size_t)n * GK;
        row[k]         = h;
        row[K + k]     = h;
        row[2 * K + k] = l;
    }
}

// ---------------------------------------------------------------------------
// bf16 mma.sync GEMM: C[M,N] fp32 = A'[M,GK] x B'[N,GK]^T
// 128x128 CTA tile, BK=32, 256 threads (2x4 warps, 64x32 warp tile),
// cp.async double-buffered smem, ldmatrix fragments.
// ---------------------------------------------------------------------------
#define BMt 128
#define BNt 128
#define BKt 32
#define PADt 40                 // bf16 per smem row (80B stride; conflict-free ldmatrix)
#define NCHt (GK/BKt)           // 96

__global__ __launch_bounds__(256) void gemm_mma(const __nv_bfloat16* __restrict__ A,
                                                const __nv_bfloat16* __restrict__ Bt,
                                                float* __restrict__ C, int N) {
    __shared__ __nv_bfloat16 As[2][BMt * PADt];
    __shared__ __nv_bfloat16 Bs[2][BNt * PADt];

    int t = threadIdx.x, w = t >> 5, lane = t & 31;
    int m0 = blockIdx.y * BMt, n0 = blockIdx.x * BNt;
    int wm = (w >> 2) * 64;     // warp m offset (2 warps in m)
    int wn = (w & 3) * 32;      // warp n offset (4 warps in n)

    float acc[4][4][4];         // [m-tile 16][n-tile 8][frag]
#pragma unroll
    for (int i = 0; i < 4; i++)
#pragma unroll
        for (int j = 0; j < 4; j++)
#pragma unroll
            for (int r = 0; r < 4; r++) acc[i][j][r] = 0.f;

    uint32_t asb = smem_u32(As), bsb = smem_u32(Bs);

    // Loader mapping: 512 16B-chunks per tile, 2 per thread.
    int lrow0 = (t * 2) >> 2, lch0 = (t * 2) & 3;        // chunk 0
    int lrow1 = (t * 2 + 1) >> 2, lch1 = (t * 2 + 1) & 3; // chunk 1

    const __nv_bfloat16* Ab = A  + (size_t)m0 * GK;
    const __nv_bfloat16* Bb = Bt + (size_t)n0 * GK;

    auto load_tile = [&](int kc, int buf) {
        uint32_t ab = asb + buf * (BMt * PADt * 2);
        uint32_t bb = bsb + buf * (BNt * PADt * 2);
        const __nv_bfloat16* Ak = Ab + kc * BKt;
        const __nv_bfloat16* Bk = Bb + kc * BKt;
        cp16(ab + (lrow0 * PADt + lch0 * 8) * 2, Ak + (size_t)lrow0 * GK + lch0 * 8);
        cp16(ab + (lrow1 * PADt + lch1 * 8) * 2, Ak + (size_t)lrow1 * GK + lch1 * 8);
        cp16(bb + (lrow0 * PADt + lch0 * 8) * 2, Bk + (size_t)lrow0 * GK + lch0 * 8);
        cp16(bb + (lrow1 * PADt + lch1 * 8) * 2, Bk + (size_t)lrow1 * GK + lch1 * 8);
        CP_COMMIT();
    };

    load_tile(0, 0);

    int li = lane >> 3;         // ldmatrix matrix index 0..3
    int lr = lane & 7;          // row within 8x8 matrix

    for (int kc = 0; kc < NCHt; kc++) {
        int buf = kc & 1;
        if (kc + 1 < NCHt) load_tile(kc + 1, buf ^ 1);
        if (kc + 1 < NCHt) { CP_WAIT(1); } else { CP_WAIT(0); }
        __syncthreads();

        uint32_t ab = asb + buf * (BMt * PADt * 2);
        uint32_t bb = bsb + buf * (BNt * PADt * 2);

#pragma unroll
        for (int ks = 0; ks < 2; ks++) {
            int k0 = ks * 16;
            uint32_t a[4][4];
#pragma unroll
            for (int mt = 0; mt < 4; mt++) {
                int row = wm + mt * 16 + (li & 1) * 8 + lr;
                int col = k0 + (li >> 1) * 8;
                ldsm4(a[mt][0], a[mt][1], a[mt][2], a[mt][3],
                      ab + (row * PADt + col) * 2);
            }
            uint32_t b[2][4];
#pragma unroll
            for (int p = 0; p < 2; p++) {
                int row = wn + p * 16 + (li >> 1) * 8 + lr;
                int col = k0 + (li & 1) * 8;
                ldsm4(b[p][0], b[p][1], b[p][2], b[p][3],
                      bb + (row * PADt + col) * 2);
            }
#pragma unroll
            for (int mt = 0; mt < 4; mt++)
#pragma unroll
                for (int nt = 0; nt < 4; nt++) {
                    int p = nt >> 1, off = (nt & 1) * 2;
                    mma16816(acc[mt][nt], a[mt][0], a[mt][1], a[mt][2], a[mt][3],
                             b[p][off], b[p][off + 1]);
                }
        }
        __syncthreads();
    }

    // Epilogue
    int cr = lane >> 2, cc = (lane & 3) * 2;
#pragma unroll
    for (int mt = 0; mt < 4; mt++)
#pragma unroll
        for (int nt = 0; nt < 4; nt++) {
            float* Cp = C + (size_t)(m0 + wm + mt * 16 + cr) * N + n0 + wn + nt * 8 + cc;
            *(float2*)Cp = make_float2(acc[mt][nt][0], acc[mt][nt][1]);
            *(float2*)(Cp + 8 * (size_t)N) = make_float2(acc[mt][nt][2], acc[mt][nt][3]);
        }
}

// ---------------------------------------------------------------------------
// RoPE in place
// ---------------------------------------------------------------------------
__global__ __launch_bounds__(256) void rope_kernel(float* __restrict__ q,
                                                   float* __restrict__ kout,
                                                   const float* __restrict__ cosT,
                                                   const float* __restrict__ sinT) {
    int idx = blockIdx.x * blockDim.x + threadIdx.x;
    const int total = BATCH * SEQ * (NH + NKV) * (HD / 2);
    if (idx >= total) return;
    int j = idx & 31;
    int rest = idx >> 5;
    int head = rest % (NH + NKV);
    int s = (rest / (NH + NKV)) % SEQ;
    int b = rest / ((NH + NKV) * SEQ);

    float c  = cosT[s * 32 + j];
    float sn = sinT[s * 32 + j];
    float* base;
    float scale;
    if (head < NH) {
        base = q + ((((size_t)b * SEQ + s) * NH + head) << 6);
        scale = 0.125f;
    } else {
        base = kout + ((((size_t)b * SEQ + s) * NKV + (head - NH)) << 6);
        scale = 1.0f;
    }
    float x1 = base[j];
    float x2 = base[j + 32];
    base[j]      = (x1 * c - x2 * sn) * scale;
    base[j + 32] = (x2 * c + x1 * sn) * scale;
}

// ---------------------------------------------------------------------------
// Flash attention fp32 (unchanged; passed R1)
// ---------------------------------------------------------------------------
#define SPAD 68
#define ATTN_SMEM ((3*64*SPAD + 128) * (int)sizeof(float))

__global__ __launch_bounds__(128) void attn_kernel(const float* __restrict__ Q,
                                                   const float* __restrict__ Kg,
                                                   const float* __restrict__ Vg,
                                                   float* __restrict__ O) {
    extern __shared__ float smf[];
    float* qs    = smf;
    float* kvs   = smf + 64 * SPAD;
    float* ss    = smf + 2 * 64 * SPAD;
    float* alpha = smf + 3 * 64 * SPAD;
    float* linv  = alpha + 64;

    int t  = threadIdx.x;
    int qt = blockIdx.x;
    int h  = blockIdx.y;
    int b  = blockIdx.z;
    int tx = t & 15, ty = t >> 4;
    int i0 = tx * 4;
    int j0 = ty * 8;

    const float* Qb = Q + ((((size_t)b * SEQ) + (size_t)qt * 64) * NH + h) * HD;
#pragma unroll
    for (int i = 0; i < 8; i++) {
        int idx = t + 128 * i;
        int row = idx >> 4, c4 = idx & 15;
        float4 v = *(const float4*)(Qb + (size_t)row * (NH * HD) + c4 * 4);
        qs[(c4 * 4 + 0) * SPAD + row] = v.x;
        qs[(c4 * 4 + 1) * SPAD + row] = v.y;
        qs[(c4 * 4 + 2) * SPAD + row] = v.z;
        qs[(c4 * 4 + 3) * SPAD + row] = v.w;
    }

    float m_i = -1e30f, l_i = 0.f;
    float o[4][8];
#pragma unroll
    for (int r = 0; r < 4; r++)
#pragma unroll
        for (int c = 0; c < 8; c++) o[r][c] = 0.f;

    int kvh = h >> 2;
    const float* Kb = Kg + ((size_t)b * SEQ * NKV + kvh) * HD;
    const float* Vb = Vg + ((size_t)b * SEQ * NKV + kvh) * HD;

    for (int kt = 0; kt <= qt; kt++) {
        __syncthreads();
        const float* Kt = Kb + (size_t)kt * 64 * (NKV * HD);
#pragma unroll
        for (int i = 0; i < 8; i++) {
            int idx = t + 128 * i;
            int row = idx >> 4, c4 = idx & 15;
            float4 v = *(const float4*)(Kt + (size_t)row * (NKV * HD) + c4 * 4);
            kvs[(c4 * 4 + 0) * SPAD + row] = v.x;
            kvs[(c4 * 4 + 1) * SPAD + row] = v.y;
            kvs[(c4 * 4 + 2) * SPAD + row] = v.z;
            kvs[(c4 * 4 + 3) * SPAD + row] = v.w;
        }
        __syncthreads();

        float s[4][8];
#pragma unroll
        for (int r = 0; r < 4; r++)
#pragma unroll
            for (int c = 0; c < 8; c++) s[r][c] = 0.f;
#pragma unroll 8
        for (int kk = 0; kk < 64; kk++) {
            float4 a  = *(float4*)(qs  + kk * SPAD + i0);
            float4 b0 = *(float4*)(kvs + kk * SPAD + j0);
            float4 b1 = *(float4*)(kvs + kk * SPAD + j0 + 4);
            float av[4] = {a.x, a.y, a.z, a.w};
            float bv[8] = {b0.x, b0.y, b0.z, b0.w, b1.x, b1.y, b1.z, b1.w};
#pragma unroll
            for (int r = 0; r < 4; r++)
#pragma unroll
                for (int c = 0; c < 8; c++) s[r][c] += av[r] * bv[c];
        }
        if (kt == qt) {
#pragma unroll
            for (int r = 0; r < 4; r++)
#pragma unroll
                for (int c = 0; c < 8; c++)
                    if (j0 + c > i0 + r) s[r][c] = -1e30f;
        }
        __syncthreads();

#pragma unroll
        for (int c = 0; c < 8; c++) {
            float4 sv = make_float4(s[0][c], s[1][c], s[2][c], s[3][c]);
            *(float4*)(ss + (j0 + c) * SPAD + i0) = sv;
        }
        const float* Vt = Vb + (size_t)kt * 64 * (NKV * HD);
#pragma unroll
        for (int i = 0; i < 8; i++) {
            int idx = t + 128 * i;
            int row = idx >> 4, c4 = idx & 15;
            float4 v = *(const float4*)(Vt + (size_t)row * (NKV * HD) + c4 * 4);
            *(float4*)(kvs + row * SPAD + c4 * 4) = v;
        }
        __syncthreads();

        if (t < 64) {
            float mx = m_i;
#pragma unroll 8
            for (int kk = 0; kk < 64; kk++) mx = fmaxf(mx, ss[kk * SPAD + t]);
            float al = __expf(m_i - mx);
            float lsum = 0.f;
#pragma unroll 8
            for (int kk = 0; kk < 64; kk++) {
                float p = __expf(ss[kk * SPAD + t] - mx);
                ss[kk * SPAD + t] = p;
                lsum += p;
            }
            l_i = l_i * al + lsum;
            m_i = mx;
            alpha[t] = al;
        }
        __syncthreads();

        float al4[4];
#pragma unroll
        for (int r = 0; r < 4; r++) al4[r] = alpha[i0 + r];
#pragma unroll
        for (int r = 0; r < 4; r++)
#pragma unroll
            for (int c = 0; c < 8; c++) o[r][c] *= al4[r];
#pragma unroll 8
        for (int kk = 0; kk < 64; kk++) {
            float4 p  = *(float4*)(ss  + kk * SPAD + i0);
            float4 v0 = *(float4*)(kvs + kk * SPAD + j0);
            float4 v1 = *(float4*)(kvs + kk * SPAD + j0 + 4);
            float pv[4] = {p.x, p.y, p.z, p.w};
            float vv[8] = {v0.x, v0.y, v0.z, v0.w, v1.x, v1.y, v1.z, v1.w};
#pragma unroll
            for (int r = 0; r < 4; r++)
#pragma unroll
                for (int c = 0; c < 8; c++) o[r][c] += pv[r] * vv[c];
        }
    }

    if (t < 64) linv[t] = 1.f / l_i;
    __syncthreads();

    float* Ob = O + ((((size_t)b * SEQ) + (size_t)qt * 64) * NH + h) * HD;
#pragma unroll
    for (int r = 0; r < 4; r++) {
        float inv = linv[i0 + r];
        float4 c0 = make_float4(o[r][0] * inv, o[r][1] * inv, o[r][2] * inv, o[r][3] * inv);
        float4 c1 = make_float4(o[r][4] * inv, o[r][5] * inv, o[r][6] * inv, o[r][7] * inv);
        float* Op = Ob + (size_t)(i0 + r) * (NH * HD) + j0;
        *(float4*)(Op)     = c0;
        *(float4*)(Op + 4) = c1;
    }
}

// ---------------------------------------------------------------------------
extern "C" void kernel_launch(void* const* d_in, const int* in_sizes, int n_in,
                              void* d_out, int out_size) {
    const float* x    = (const float*)d_in[0];
    const float* cosT = (const float*)d_in[1];
    const float* sinT = (const float*)d_in[2];
    // d_in[3] = mask: unused (hard causal mask identical in fp32)
    const float* wq   = (const float*)d_in[4];
    const float* wk   = (const float*)d_in[5];
    const float* wv   = (const float*)d_in[6];
    const float* wo   = (const float*)d_in[7];

    float* out  = (float*)d_out;
    float* kout = out + OUT_ELEMS;
    float* vout = out + OUT_ELEMS + KV_ELEMS;

    float *qbuf, *aobuf;
    __nv_bfloat16 *xc, *aoc, *wqt, *wkt, *wvt, *wot;
    cudaGetSymbolAddress((void**)&qbuf,  g_q);
    cudaGetSymbolAddress((void**)&aobuf, g_ao);
    cudaGetSymbolAddress((void**)&xc,  g_xc);
    cudaGetSymbolAddress((void**)&aoc, g_aoc);
    cudaGetSymbolAddress((void**)&wqt, g_wqt);
    cudaGetSymbolAddress((void**)&wkt, g_wkt);
    cudaGetSymbolAddress((void**)&wvt, g_wvt);
    cudaGetSymbolAddress((void**)&wot, g_wot);

    cudaFuncSetAttribute(attn_kernel, cudaFuncAttributeMaxDynamicSharedMemorySize, ATTN_SMEM);

    // Split conversions
    conv_a<<<(MTOT * DMODEL / 4 + 255) / 256, 256>>>(x, xc);
    dim3 wb(32, 8);
    conv_w<<<dim3((NH * HD) / 32, DMODEL / 32), wb>>>(wq, wqt, NH * HD);
    conv_w<<<dim3((NKV * HD) / 32, DMODEL / 32), wb>>>(wk, wkt, NKV * HD);
    conv_w<<<dim3((NKV * HD) / 32, DMODEL / 32), wb>>>(wv, wvt, NKV * HD);
    conv_w<<<dim3(DMODEL / 32, DMODEL / 32), wb>>>(wo, wot, DMODEL);

    // Projections on tensor cores (mma.sync bf16, split for fp32 accuracy)
    gemm_mma<<<dim3((NH * HD) / 128, MTOT / 128), 256>>>(xc, wqt, qbuf, NH * HD);
    gemm_mma<<<dim3((NKV * HD) / 128, MTOT / 128), 256>>>(xc, wkt, kout, NKV * HD);
    gemm_mma<<<dim3((NKV * HD) / 128, MTOT / 128), 256>>>(xc, wvt, vout, NKV * HD);

    // RoPE
    {
        int total = BATCH * SEQ * (NH + NKV) * (HD / 2);
        rope_kernel<<<(total + 255) / 256, 256>>>(qbuf, kout, cosT, sinT);
    }

    // Flash attention (fp32)
    attn_kernel<<<dim3(SEQ / 64, NH, BATCH), 128, ATTN_SMEM>>>(qbuf, kout, vout, aobuf);

    // Output projection
    conv_a<<<(MTOT * DMODEL / 4 + 255) / 256, 256>>>(aobuf, aoc);
    gemm_mma<<<dim3(DMODEL / 128, MTOT / 128), 256>>>(aoc, wot, out, DMODEL);
}

// round 4
// speedup vs baseline: 1.9037x; 1.5046x over previous
#include <cuda_runtime.h>
#include <cuda_bf16.h>
#include <cstdint>

// Problem constants
#define BATCH 2
#define SEQ 2048
#define DMODEL 1024
#define NH 16
#define NKV 4
#define HD 64
#define OUT_ELEMS  (BATCH*SEQ*DMODEL)
#define KV_ELEMS   (BATCH*SEQ*NKV*HD)

#define MTOT (BATCH*SEQ)        // 4096
#define GK   (3*DMODEL)         // 3072 split-K (hi|lo|hi vs hi|hi|lo)

// ---------------------------------------------------------------------------
// Scratch (device globals; no runtime allocation allowed)
// ---------------------------------------------------------------------------
__device__ float g_q [MTOT*NH*HD];                 // q after RoPE+scale
__device__ float g_ao[MTOT*NH*HD];                 // attention output
__device__ __nv_bfloat16 g_xc [MTOT*GK];           // x split [M, 3K]
__device__ __nv_bfloat16 g_aoc[MTOT*GK];           // ao split [M, 3K]
__device__ __nv_bfloat16 g_wqt[(NH*HD)*GK];        // wq^T split [N, 3K]
__device__ __nv_bfloat16 g_wkt[(NKV*HD)*GK];
__device__ __nv_bfloat16 g_wvt[(NKV*HD)*GK];
__device__ __nv_bfloat16 g_wot[DMODEL*GK];
// Attention operands (pre-split bf16)
__device__ __nv_bfloat16 g_qb [BATCH*NH*SEQ*192];   // [b][h][s][hi|lo|hi]
__device__ __nv_bfloat16 g_kb [BATCH*NKV*SEQ*192];  // [b][kvh][s][hi|hi|lo]
__device__ __nv_bfloat16 g_vhi[BATCH*NKV*HD*SEQ];   // [b][kvh][d][s] transposed
__device__ __nv_bfloat16 g_vlo[BATCH*NKV*HD*SEQ];

// ---------------------------------------------------------------------------
// Baseline-PTX helpers (sm_80-era instructions only)
// ---------------------------------------------------------------------------
__device__ __forceinline__ uint32_t smem_u32(const void* p) {
    uint32_t a;
    asm("{ .reg .u64 t; cvta.to.shared.u64 t, %1; cvt.u32.u64 %0, t; }" : "=r"(a) : "l"(p));
    return a;
}
__device__ __forceinline__ void cp16(uint32_t saddr, const void* g) {
    asm volatile("cp.async.cg.shared.global [%0], [%1], 16;" :: "r"(saddr), "l"(g) : "memory");
}
#define CP_COMMIT() asm volatile("cp.async.commit_group;" ::: "memory")
#define CP_WAIT(n)  asm volatile("cp.async.wait_group %0;" :: "n"(n) : "memory")

__device__ __forceinline__ void ldsm4(uint32_t& r0, uint32_t& r1, uint32_t& r2, uint32_t& r3,
                                      uint32_t a) {
    asm volatile("ldmatrix.sync.aligned.m8n8.x4.shared.b16 {%0,%1,%2,%3}, [%4];"
                 : "=r"(r0), "=r"(r1), "=r"(r2), "=r"(r3) : "r"(a));
}
__device__ __forceinline__ void mma16816(float* c, uint32_t a0, uint32_t a1, uint32_t a2,
                                         uint32_t a3, uint32_t b0, uint32_t b1) {
    asm volatile(
        "mma.sync.aligned.m16n8k16.row.col.f32.bf16.bf16.f32 "
        "{%0,%1,%2,%3},{%4,%5,%6,%7},{%8,%9},{%0,%1,%2,%3};"
        : "+f"(c[0]), "+f"(c[1]), "+f"(c[2]), "+f"(c[3])
        : "r"(a0), "r"(a1), "r"(a2), "r"(a3), "r"(b0), "r"(b1));
}
// pack two floats to bf16x2 (lo = x, hi = y)
__device__ __forceinline__ uint32_t pack_bf16(float x, float y) {
    uint32_t r;
    asm("cvt.rn.bf16x2.f32 %0, %1, %2;" : "=r"(r) : "f"(y), "f"(x));
    return r;
}

// ---------------------------------------------------------------------------
// Split conversions: v -> (hi, lo) bf16 with hi = rn(v), lo = rn(v - hi)
// ---------------------------------------------------------------------------
__device__ __forceinline__ void split_bf16(float v, __nv_bfloat16& hi, __nv_bfloat16& lo) {
    hi = __float2bfloat16(v);
    lo = __float2bfloat16(v - __bfloat162float(hi));
}

// A-side: src [M, K] fp32 -> dst [M, 3K] = [hi | lo | hi]
__global__ __launch_bounds__(256) void conv_a(const float* __restrict__ src,
                                              __nv_bfloat16* __restrict__ dst) {
    int idx = blockIdx.x * blockDim.x + threadIdx.x;   // per float4
    const int K = DMODEL;
    if (idx >= MTOT * K / 4) return;
    int flat = idx * 4;
    int m = flat / K, k = flat % K;
    float4 v = *(const float4*)(src + flat);
    float vv[4] = {v.x, v.y, v.z, v.w};
    __nv_bfloat16 h[4], l[4];
#pragma unroll
    for (int j = 0; j < 4; j++) split_bf16(vv[j], h[j], l[j]);
    __nv_bfloat16* row = dst + (size_t)m * GK;
    *(uint2*)(row + k)         = *(uint2*)h;
    *(uint2*)(row + K + k)     = *(uint2*)l;
    *(uint2*)(row + 2 * K + k) = *(uint2*)h;
}

// B-side: src [K, N] fp32 -> dst [N, 3K] = [hi | hi | lo] (transposed)
__global__ void conv_w(const float* __restrict__ src, __nv_bfloat16* __restrict__ dst, int N) {
    __shared__ float tile[32][33];
    const int K = DMODEL;
    int k0 = blockIdx.y * 32, n0 = blockIdx.x * 32;
    int tx = threadIdx.x, ty = threadIdx.y;   // 32 x 8
#pragma unroll
    for (int i = 0; i < 32; i += 8)
        tile[ty + i][tx] = src[(size_t)(k0 + ty + i) * N + n0 + tx];
    __syncthreads();
#pragma unroll
    for (int i = 0; i < 32; i += 8) {
        int n = n0 + ty + i, k = k0 + tx;
        __nv_bfloat16 h, l;
        split_bf16(tile[tx][ty + i], h, l);
        __nv_bfloat16* row = dst + (size_t)n * GK;
        row[k]         = h;
        row[K + k]     = h;
        row[2 * K + k] = l;
    }
}

// ---------------------------------------------------------------------------
// bf16 mma.sync GEMM (unchanged from R3)
// ---------------------------------------------------------------------------
#define BMt 128
#define BNt 128
#define BKt 32
#define PADt 40
#define NCHt (GK/BKt)

__global__ __launch_bounds__(256) void gemm_mma(const __nv_bfloat16* __restrict__ A,
                                                const __nv_bfloat16* __restrict__ Bt,
                                                float* __restrict__ C, int N) {
    __shared__ __nv_bfloat16 As[2][BMt * PADt];
    __shared__ __nv_bfloat16 Bs[2][BNt * PADt];

    int t = threadIdx.x, w = t >> 5, lane = t & 31;
    int m0 = blockIdx.y * BMt, n0 = blockIdx.x * BNt;
    int wm = (w >> 2) * 64;
    int wn = (w & 3) * 32;

    float acc[4][4][4];
#pragma unroll
    for (int i = 0; i < 4; i++)
#pragma unroll
        for (int j = 0; j < 4; j++)
#pragma unroll
            for (int r = 0; r < 4; r++) acc[i][j][r] = 0.f;

    uint32_t asb = smem_u32(As), bsb = smem_u32(Bs);

    int lrow0 = (t * 2) >> 2, lch0 = (t * 2) & 3;
    int lrow1 = (t * 2 + 1) >> 2, lch1 = (t * 2 + 1) & 3;

    const __nv_bfloat16* Ab = A  + (size_t)m0 * GK;
    const __nv_bfloat16* Bb = Bt + (size_t)n0 * GK;

    auto load_tile = [&](int kc, int buf) {
        uint32_t ab = asb + buf * (BMt * PADt * 2);
        uint32_t bb = bsb + buf * (BNt * PADt * 2);
        const __nv_bfloat16* Ak = Ab + kc * BKt;
        const __nv_bfloat16* Bk = Bb + kc * BKt;
        cp16(ab + (lrow0 * PADt + lch0 * 8) * 2, Ak + (size_t)lrow0 * GK + lch0 * 8);
        cp16(ab + (lrow1 * PADt + lch1 * 8) * 2, Ak + (size_t)lrow1 * GK + lch1 * 8);
        cp16(bb + (lrow0 * PADt + lch0 * 8) * 2, Bk + (size_t)lrow0 * GK + lch0 * 8);
        cp16(bb + (lrow1 * PADt + lch1 * 8) * 2, Bk + (size_t)lrow1 * GK + lch1 * 8);
        CP_COMMIT();
    };

    load_tile(0, 0);

    int li = lane >> 3;
    int lr = lane & 7;

    for (int kc = 0; kc < NCHt; kc++) {
        int buf = kc & 1;
        if (kc + 1 < NCHt) load_tile(kc + 1, buf ^ 1);
        if (kc + 1 < NCHt) { CP_WAIT(1); } else { CP_WAIT(0); }
        __syncthreads();

        uint32_t ab = asb + buf * (BMt * PADt * 2);
        uint32_t bb = bsb + buf * (BNt * PADt * 2);

#pragma unroll
        for (int ks = 0; ks < 2; ks++) {
            int k0 = ks * 16;
            uint32_t a[4][4];
#pragma unroll
            for (int mt = 0; mt < 4; mt++) {
                int row = wm + mt * 16 + (li & 1) * 8 + lr;
                int col = k0 + (li >> 1) * 8;
                ldsm4(a[mt][0], a[mt][1], a[mt][2], a[mt][3],
                      ab + (row * PADt + col) * 2);
            }
            uint32_t b[2][4];
#pragma unroll
            for (int p = 0; p < 2; p++) {
                int row = wn + p * 16 + (li >> 1) * 8 + lr;
                int col = k0 + (li & 1) * 8;
                ldsm4(b[p][0], b[p][1], b[p][2], b[p][3],
                      bb + (row * PADt + col) * 2);
            }
#pragma unroll
            for (int mt = 0; mt < 4; mt++)
#pragma unroll
                for (int nt = 0; nt < 4; nt++) {
                    int p = nt >> 1, off = (nt & 1) * 2;
                    mma16816(acc[mt][nt], a[mt][0], a[mt][1], a[mt][2], a[mt][3],
                             b[p][off], b[p][off + 1]);
                }
        }
        __syncthreads();
    }

    int cr = lane >> 2, cc = (lane & 3) * 2;
#pragma unroll
    for (int mt = 0; mt < 4; mt++)
#pragma unroll
        for (int nt = 0; nt < 4; nt++) {
            float* Cp = C + (size_t)(m0 + wm + mt * 16 + cr) * N + n0 + wn + nt * 8 + cc;
            *(float2*)Cp = make_float2(acc[mt][nt][0], acc[mt][nt][1]);
            *(float2*)(Cp + 8 * (size_t)N) = make_float2(acc[mt][nt][2], acc[mt][nt][3]);
        }
}

// ---------------------------------------------------------------------------
// RoPE in place
// ---------------------------------------------------------------------------
__global__ __launch_bounds__(256) void rope_kernel(float* __restrict__ q,
                                                   float* __restrict__ kout,
                                                   const float* __restrict__ cosT,
                                                   const float* __restrict__ sinT) {
    int idx = blockIdx.x * blockDim.x + threadIdx.x;
    const int total = BATCH * SEQ * (NH + NKV) * (HD / 2);
    if (idx >= total) return;
    int j = idx & 31;
    int rest = idx >> 5;
    int head = rest % (NH + NKV);
    int s = (rest / (NH + NKV)) % SEQ;
    int b = rest / ((NH + NKV) * SEQ);

    float c  = cosT[s * 32 + j];
    float sn = sinT[s * 32 + j];
    float* base;
    float scale;
    if (head < NH) {
        base = q + ((((size_t)b * SEQ + s) * NH + head) << 6);
        scale = 0.125f;
    } else {
        base = kout + ((((size_t)b * SEQ + s) * NKV + (head - NH)) << 6);
        scale = 1.0f;
    }
    float x1 = base[j];
    float x2 = base[j + 32];
    base[j]      = (x1 * c - x2 * sn) * scale;
    base[j + 32] = (x2 * c + x1 * sn) * scale;
}

// ---------------------------------------------------------------------------
// Attention prep: pre-split Q/K to [.,192] bf16, V to transposed hi/lo tensors
// ---------------------------------------------------------------------------
__global__ __launch_bounds__(256) void prep_q(const float* __restrict__ q,
                                              __nv_bfloat16* __restrict__ dst) {
    int i = blockIdx.x * 256 + threadIdx.x;          // one per 8 elems
    if (i >= MTOT * NH * HD / 8) return;
    int o8 = (i * 8) % HD;
    int row = (i * 8) / HD;                          // [b][s][h]
    int h = row % NH, s = (row / NH) % SEQ, b = row / (NH * SEQ);
    float4 v0 = *(const float4*)(q + (size_t)row * HD + o8);
    float4 v1 = *(const float4*)(q + (size_t)row * HD + o8 + 4);
    float vv[8] = {v0.x, v0.y, v0.z, v0.w, v1.x, v1.y, v1.z, v1.w};
    __nv_bfloat16 hi[8], lo[8];
#pragma unroll
    for (int j = 0; j < 8; j++) split_bf16(vv[j], hi[j], lo[j]);
    __nv_bfloat16* d = dst + ((size_t)(b * NH + h) * SEQ + s) * 192;
    *(uint4*)(d + o8)       = *(uint4*)hi;
    *(uint4*)(d + 64 + o8)  = *(uint4*)lo;
    *(uint4*)(d + 128 + o8) = *(uint4*)hi;
}

__global__ __launch_bounds__(256) void prep_k(const float* __restrict__ k,
                                              __nv_bfloat16* __restrict__ dst) {
    int i = blockIdx.x * 256 + threadIdx.x;
    if (i >= MTOT * NKV * HD / 8) return;
    int o8 = (i * 8) % HD;
    int row = (i * 8) / HD;                          // [b][s][kvh]
    int kvh = row % NKV, s = (row / NKV) % SEQ, b = row / (NKV * SEQ);
    float4 v0 = *(const float4*)(k + (size_t)row * HD + o8);
    float4 v1 = *(const float4*)(k + (size_t)row * HD + o8 + 4);
    float vv[8] = {v0.x, v0.y, v0.z, v0.w, v1.x, v1.y, v1.z, v1.w};
    __nv_bfloat16 hi[8], lo[8];
#pragma unroll
    for (int j = 0; j < 8; j++) split_bf16(vv[j], hi[j], lo[j]);
    __nv_bfloat16* d = dst + ((size_t)(b * NKV + kvh) * SEQ + s) * 192;
    *(uint4*)(d + o8)       = *(uint4*)hi;
    *(uint4*)(d + 64 + o8)  = *(uint4*)hi;
    *(uint4*)(d + 128 + o8) = *(uint4*)lo;
}

// V transpose + split: vout [b][s][kvh][d] -> gvhi/gvlo [b*NKV+kvh][d][s]
__global__ void prep_v(const float* __restrict__ v,
                       __nv_bfloat16* __restrict__ vhi,
                       __nv_bfloat16* __restrict__ vlo) {
    __shared__ float tile[32][33];
    int bkv = blockIdx.z;
    int b = bkv / NKV, kvh = bkv % NKV;
    int s0 = blockIdx.x * 32, d0 = blockIdx.y * 32;
    int tx = threadIdx.x, ty = threadIdx.y;          // 32 x 8
#pragma unroll
    for (int i = 0; i < 32; i += 8)
        tile[ty + i][tx] = v[(((size_t)b * SEQ + s0 + ty + i) * NKV + kvh) * HD + d0 + tx];
    __syncthreads();
#pragma unroll
    for (int i = 0; i < 32; i += 8) {
        int d = d0 + ty + i, s = s0 + tx;
        __nv_bfloat16 h, l;
        split_bf16(tile[tx][ty + i], h, l);
        size_t off = ((size_t)bkv * HD + d) * SEQ + s;
        vhi[off] = h;
        vlo[off] = l;
    }
}

// ---------------------------------------------------------------------------
// Tensor-core flash attention, split-bf16 precision.
// CTA: 64 queries x one (b,h); 128 threads (4 warps, 16 q-rows each).
// Key tiles of 64. Contraction K=192 for both QK' and P'V'.
// ---------------------------------------------------------------------------
#define APAD 200                         // bf16 row stride (400B, conflict-free)
#define ATTN2_SMEM (3 * 64 * APAD * 2)   // qs, ks, vs

__global__ __launch_bounds__(128) void attn_mma(const __nv_bfloat16* __restrict__ Qb,
                                                const __nv_bfloat16* __restrict__ Kb,
                                                const __nv_bfloat16* __restrict__ Vhi,
                                                const __nv_bfloat16* __restrict__ Vlo,
                                                float* __restrict__ O) {
    extern __shared__ __nv_bfloat16 sb[];
    __nv_bfloat16* qs = sb;
    __nv_bfloat16* ks = sb + 64 * APAD;
    __nv_bfloat16* vs = sb + 2 * 64 * APAD;
    uint32_t qsa = smem_u32(qs), ksa = smem_u32(ks), vsa = smem_u32(vs);

    int t = threadIdx.x, w = t >> 5, lane = t & 31;
    int qt = blockIdx.x, h = blockIdx.y, b = blockIdx.z;
    int kvh = h >> 2;
    int li = lane >> 3, lr = lane & 7;
    int r0 = lane >> 2;                // row within warp's 16 (and r0+8)
    int cc = (lane & 3) * 2;           // col pair base within 8-col tile

    // Load Q' tile [64][192] once
    const __nv_bfloat16* qsrc = Qb + ((size_t)(b * NH + h) * SEQ + (size_t)qt * 64) * 192;
#pragma unroll
    for (int i = 0; i < 12; i++) {
        int c = t + 128 * i;
        int row = c / 24, seg = c % 24;
        cp16(qsa + (row * APAD + seg * 8) * 2, qsrc + (size_t)row * 192 + seg * 8);
    }
    CP_COMMIT();

    float m0 = -1e30f, m1 = -1e30f, l0 = 0.f, l1 = 0.f;
    float of[8][4];
#pragma unroll
    for (int j = 0; j < 8; j++)
#pragma unroll
        for (int e = 0; e < 4; e++) of[j][e] = 0.f;

    const __nv_bfloat16* ksrc0 = Kb + (size_t)(b * NKV + kvh) * SEQ * 192;
    const __nv_bfloat16* vh0 = Vhi + (size_t)(b * NKV + kvh) * HD * SEQ;
    const __nv_bfloat16* vl0 = Vlo + (size_t)(b * NKV + kvh) * HD * SEQ;

    for (int kt = 0; kt <= qt; kt++) {
        // Load K' tile [64][192]
        const __nv_bfloat16* ksrc = ksrc0 + (size_t)kt * 64 * 192;
#pragma unroll
        for (int i = 0; i < 12; i++) {
            int c = t + 128 * i;
            int row = c / 24, seg = c % 24;
            cp16(ksa + (row * APAD + seg * 8) * 2, ksrc + (size_t)row * 192 + seg * 8);
        }
        // Load V' tile [64 hd][192] = [Vhi | Vhi | Vlo] over 64 keys
#pragma unroll
        for (int i = 0; i < 12; i++) {
            int c = t + 128 * i;
            int d = c / 24, seg = c % 24;
            const __nv_bfloat16* src;
            int kc = (seg & 7) * 8;
            if (seg < 16) src = vh0 + (size_t)d * SEQ + kt * 64 + kc;
            else          src = vl0 + (size_t)d * SEQ + kt * 64 + kc;
            cp16(vsa + (d * APAD + seg * 8) * 2, src);
        }
        CP_COMMIT();
        CP_WAIT(0);
        __syncthreads();

        // ---- S = Q' K'^T (fp32 accum) ----
        float sf[8][4];
#pragma unroll
        for (int j = 0; j < 8; j++)
#pragma unroll
            for (int e = 0; e < 4; e++) sf[j][e] = 0.f;
#pragma unroll
        for (int ks12 = 0; ks12 < 12; ks12++) {
            int k0 = ks12 * 16;
            uint32_t a0, a1, a2, a3;
            ldsm4(a0, a1, a2, a3,
                  qsa + ((w * 16 + (li & 1) * 8 + lr) * APAD + k0 + (li >> 1) * 8) * 2);
#pragma unroll
            for (int p = 0; p < 4; p++) {
                uint32_t b0, b1, b2, b3;
                ldsm4(b0, b1, b2, b3,
                      ksa + ((p * 16 + (li >> 1) * 8 + lr) * APAD + k0 + (li & 1) * 8) * 2);
                mma16816(sf[2 * p],     a0, a1, a2, a3, b0, b1);
                mma16816(sf[2 * p + 1], a0, a1, a2, a3, b2, b3);
            }
        }

        // ---- causal mask on diagonal tile ----
        if (kt == qt) {
            int q0 = w * 16 + r0, q1 = q0 + 8;
#pragma unroll
            for (int j = 0; j < 8; j++) {
                int key = 8 * j + cc;
                if (key     > q0) sf[j][0] = -1e30f;
                if (key + 1 > q0) sf[j][1] = -1e30f;
                if (key     > q1) sf[j][2] = -1e30f;
                if (key + 1 > q1) sf[j][3] = -1e30f;
            }
        }

        // ---- online softmax (rows r0, r1 per thread, reduce over lanes&3) ----
        float mx0 = -1e30f, mx1 = -1e30f;
#pragma unroll
        for (int j = 0; j < 8; j++) {
            mx0 = fmaxf(mx0, fmaxf(sf[j][0], sf[j][1]));
            mx1 = fmaxf(mx1, fmaxf(sf[j][2], sf[j][3]));
        }
        mx0 = fmaxf(mx0, __shfl_xor_sync(0xffffffffu, mx0, 1));
        mx0 = fmaxf(mx0, __shfl_xor_sync(0xffffffffu, mx0, 2));
        mx1 = fmaxf(mx1, __shfl_xor_sync(0xffffffffu, mx1, 1));
        mx1 = fmaxf(mx1, __shfl_xor_sync(0xffffffffu, mx1, 2));
        float nm0 = fmaxf(m0, mx0), nm1 = fmaxf(m1, mx1);
        float al0 = __expf(m0 - nm0), al1 = __expf(m1 - nm1);
        m0 = nm0; m1 = nm1;

        float s0 = 0.f, s1 = 0.f;
#pragma unroll
        for (int j = 0; j < 8; j++) {
            sf[j][0] = __expf(sf[j][0] - m0); s0 += sf[j][0];
            sf[j][1] = __expf(sf[j][1] - m0); s0 += sf[j][1];
            sf[j][2] = __expf(sf[j][2] - m1); s1 += sf[j][2];
            sf[j][3] = __expf(sf[j][3] - m1); s1 += sf[j][3];
        }
        s0 += __shfl_xor_sync(0xffffffffu, s0, 1);
        s0 += __shfl_xor_sync(0xffffffffu, s0, 2);
        s1 += __shfl_xor_sync(0xffffffffu, s1, 1);
        s1 += __shfl_xor_sync(0xffffffffu, s1, 2);
        l0 = l0 * al0 + s0;
        l1 = l1 * al1 + s1;

#pragma unroll
        for (int j = 0; j < 8; j++) {
            of[j][0] *= al0; of[j][1] *= al0;
            of[j][2] *= al1; of[j][3] *= al1;
        }

        // ---- split P into bf16 A-fragments (hi & lo), FA2 register reuse ----
        uint32_t ah[4][4], alf[4][4];
#pragma unroll
        for (int kk = 0; kk < 4; kk++) {
            float c00 = sf[2 * kk][0], c01 = sf[2 * kk][1];
            float c02 = sf[2 * kk][2], c03 = sf[2 * kk][3];
            float c10 = sf[2 * kk + 1][0], c11 = sf[2 * kk + 1][1];
            float c12 = sf[2 * kk + 1][2], c13 = sf[2 * kk + 1][3];
            uint32_t h0 = pack_bf16(c00, c01), h1 = pack_bf16(c02, c03);
            uint32_t h2 = pack_bf16(c10, c11), h3 = pack_bf16(c12, c13);
            ah[kk][0] = h0; ah[kk][1] = h1; ah[kk][2] = h2; ah[kk][3] = h3;
            __nv_bfloat162 b0 = *(__nv_bfloat162*)&h0;
            __nv_bfloat162 b1 = *(__nv_bfloat162*)&h1;
            __nv_bfloat162 b2 = *(__nv_bfloat162*)&h2;
            __nv_bfloat162 b3 = *(__nv_bfloat162*)&h3;
            alf[kk][0] = pack_bf16(c00 - __bfloat162float(b0.x), c01 - __bfloat162float(b0.y));
            alf[kk][1] = pack_bf16(c02 - __bfloat162float(b1.x), c03 - __bfloat162float(b1.y));
            alf[kk][2] = pack_bf16(c10 - __bfloat162float(b2.x), c11 - __bfloat162float(b2.y));
            alf[kk][3] = pack_bf16(c12 - __bfloat162float(b3.x), c13 - __bfloat162float(b3.y));
        }

        // ---- O += P' V' : ksteps 0-3 Phi*Vhi, 4-7 Plo*Vhi, 8-11 Phi*Vlo ----
#pragma unroll
        for (int ks12 = 0; ks12 < 12; ks12++) {
            int kk = ks12 & 3, sel = ks12 >> 2;
            uint32_t* A = (sel == 1) ? alf[kk] : ah[kk];
            int k0 = ks12 * 16;
#pragma unroll
            for (int p = 0; p < 4; p++) {
                uint32_t b0, b1, b2, b3;
                ldsm4(b0, b1, b2, b3,
                      vsa + ((p * 16 + (li >> 1) * 8 + lr) * APAD + k0 + (li & 1) * 8) * 2);
                mma16816(of[2 * p],     A[0], A[1], A[2], A[3], b0, b1);
                mma16816(of[2 * p + 1], A[0], A[1], A[2], A[3], b2, b3);
            }
        }
        __syncthreads();   // done with ks/vs before next tile overwrites
    }

    // ---- epilogue ----
    float inv0 = 1.f / l0, inv1 = 1.f / l1;
    int row0 = qt * 64 + w * 16 + r0;
    int row1 = row0 + 8;
#pragma unroll
    for (int j = 0; j < 8; j++) {
        int col = 8 * j + cc;
        float* p0 = O + (((size_t)b * SEQ + row0) * NH + h) * HD + col;
        float* p1 = O + (((size_t)b * SEQ + row1) * NH + h) * HD + col;
        *(float2*)p0 = make_float2(of[j][0] * inv0, of[j][1] * inv0);
        *(float2*)p1 = make_float2(of[j][2] * inv1, of[j][3] * inv1);
    }
}

// ---------------------------------------------------------------------------
extern "C" void kernel_launch(void* const* d_in, const int* in_sizes, int n_in,
                              void* d_out, int out_size) {
    const float* x    = (const float*)d_in[0];
    const float* cosT = (const float*)d_in[1];
    const float* sinT = (const float*)d_in[2];
    // d_in[3] = mask: unused (hard causal mask identical in fp32)
    const float* wq   = (const float*)d_in[4];
    const float* wk   = (const float*)d_in[5];
    const float* wv   = (const float*)d_in[6];
    const float* wo   = (const float*)d_in[7];

    float* out  = (float*)d_out;
    float* kout = out + OUT_ELEMS;
    float* vout = out + OUT_ELEMS + KV_ELEMS;

    float *qbuf, *aobuf;
    __nv_bfloat16 *xc, *aoc, *wqt, *wkt, *wvt, *wot, *qb, *kb, *vhi, *vlo;
    cudaGetSymbolAddress((void**)&qbuf,  g_q);
    cudaGetSymbolAddress((void**)&aobuf, g_ao);
    cudaGetSymbolAddress((void**)&xc,  g_xc);
    cudaGetSymbolAddress((void**)&aoc, g_aoc);
    cudaGetSymbolAddress((void**)&wqt, g_wqt);
    cudaGetSymbolAddress((void**)&wkt, g_wkt);
    cudaGetSymbolAddress((void**)&wvt, g_wvt);
    cudaGetSymbolAddress((void**)&wot, g_wot);
    cudaGetSymbolAddress((void**)&qb,  g_qb);
    cudaGetSymbolAddress((void**)&kb,  g_kb);
    cudaGetSymbolAddress((void**)&vhi, g_vhi);
    cudaGetSymbolAddress((void**)&vlo, g_vlo);

    cudaFuncSetAttribute(attn_mma, cudaFuncAttributeMaxDynamicSharedMemorySize, ATTN2_SMEM);

    // Split conversions
    conv_a<<<(MTOT * DMODEL / 4 + 255) / 256, 256>>>(x, xc);
    dim3 wb(32, 8);
    conv_w<<<dim3((NH * HD) / 32, DMODEL / 32), wb>>>(wq, wqt, NH * HD);
    conv_w<<<dim3((NKV * HD) / 32, DMODEL / 32), wb>>>(wk, wkt, NKV * HD);
    conv_w<<<dim3((NKV * HD) / 32, DMODEL / 32), wb>>>(wv, wvt, NKV * HD);
    conv_w<<<dim3(DMODEL / 32, DMODEL / 32), wb>>>(wo, wot, DMODEL);

    // Projections on tensor cores
    gemm_mma<<<dim3((NH * HD) / 128, MTOT / 128), 256>>>(xc, wqt, qbuf, NH * HD);
    gemm_mma<<<dim3((NKV * HD) / 128, MTOT / 128), 256>>>(xc, wkt, kout, NKV * HD);
    gemm_mma<<<dim3((NKV * HD) / 128, MTOT / 128), 256>>>(xc, wvt, vout, NKV * HD);

    // RoPE
    {
        int total = BATCH * SEQ * (NH + NKV) * (HD / 2);
        rope_kernel<<<(total + 255) / 256, 256>>>(qbuf, kout, cosT, sinT);
    }

    // Attention prep (pre-split bf16 operands)
    prep_q<<<(MTOT * NH * HD / 8 + 255) / 256, 256>>>(qbuf, qb);
    prep_k<<<(MTOT * NKV * HD / 8 + 255) / 256, 256>>>(kout, kb);
    prep_v<<<dim3(SEQ / 32, HD / 32, BATCH * NKV), dim3(32, 8)>>>(vout, vhi, vlo);

    // Tensor-core flash attention
    attn_mma<<<dim3(SEQ / 64, NH, BATCH), 128, ATTN2_SMEM>>>(qb, kb, vhi, vlo, aobuf);

    // Output projection
    conv_a<<<(MTOT * DMODEL / 4 + 255) / 256, 256>>>(aobuf, aoc);
    gemm_mma<<<dim3(DMODEL / 128, MTOT / 128), 256>>>(aoc, wot, out, DMODEL);
}

// round 5
// speedup vs baseline: 2.2978x; 1.2070x over previous
#include <cuda_runtime.h>
#include <cuda_bf16.h>
#include <cstdint>

// Problem constants
#define BATCH 2
#define SEQ 2048
#define DMODEL 1024
#define NH 16
#define NKV 4
#define HD 64
#define OUT_ELEMS  (BATCH*SEQ*DMODEL)
#define KV_ELEMS   (BATCH*SEQ*NKV*HD)

#define MTOT (BATCH*SEQ)        // 4096
#define GK   (3*DMODEL)         // 3072 split-K (hi|lo|hi vs hi|hi|lo)
#define NQKV 1536               // fused QKV output width

// ---------------------------------------------------------------------------
// Scratch (device globals; no runtime allocation allowed)
// ---------------------------------------------------------------------------
__device__ float g_qkv[MTOT*NQKV];                   // fused QKV gemm output
__device__ __nv_bfloat16 g_xc   [MTOT*GK];           // x split [M, 3K]
__device__ __nv_bfloat16 g_aoc  [MTOT*GK];           // attn out split [M, 3K]
__device__ __nv_bfloat16 g_wqkvt[NQKV*GK];           // [wq|wk|wv]^T split
__device__ __nv_bfloat16 g_wot  [DMODEL*GK];
// Attention operands (pre-split bf16)
__device__ __nv_bfloat16 g_qb [BATCH*NH*SEQ*192];    // [b][h][s][hi|lo|hi]
__device__ __nv_bfloat16 g_kb [BATCH*NKV*SEQ*192];   // [b][kvh][s][hi|hi|lo]
__device__ __nv_bfloat16 g_vhi[BATCH*NKV*HD*SEQ];    // [b][kvh][d][s] transposed
__device__ __nv_bfloat16 g_vlo[BATCH*NKV*HD*SEQ];

// ---------------------------------------------------------------------------
// Baseline-PTX helpers
// ---------------------------------------------------------------------------
__device__ __forceinline__ uint32_t smem_u32(const void* p) {
    uint32_t a;
    asm("{ .reg .u64 t; cvta.to.shared.u64 t, %1; cvt.u32.u64 %0, t; }" : "=r"(a) : "l"(p));
    return a;
}
__device__ __forceinline__ void cp16(uint32_t saddr, const void* g) {
    asm volatile("cp.async.cg.shared.global [%0], [%1], 16;" :: "r"(saddr), "l"(g) : "memory");
}
#define CP_COMMIT() asm volatile("cp.async.commit_group;" ::: "memory")
#define CP_WAIT(n)  asm volatile("cp.async.wait_group %0;" :: "n"(n) : "memory")

__device__ __forceinline__ void ldsm4(uint32_t& r0, uint32_t& r1, uint32_t& r2, uint32_t& r3,
                                      uint32_t a) {
    asm volatile("ldmatrix.sync.aligned.m8n8.x4.shared.b16 {%0,%1,%2,%3}, [%4];"
                 : "=r"(r0), "=r"(r1), "=r"(r2), "=r"(r3) : "r"(a));
}
__device__ __forceinline__ void mma16816(float* c, uint32_t a0, uint32_t a1, uint32_t a2,
                                         uint32_t a3, uint32_t b0, uint32_t b1) {
    asm volatile(
        "mma.sync.aligned.m16n8k16.row.col.f32.bf16.bf16.f32 "
        "{%0,%1,%2,%3},{%4,%5,%6,%7},{%8,%9},{%0,%1,%2,%3};"
        : "+f"(c[0]), "+f"(c[1]), "+f"(c[2]), "+f"(c[3])
        : "r"(a0), "r"(a1), "r"(a2), "r"(a3), "r"(b0), "r"(b1));
}
__device__ __forceinline__ uint32_t pack_bf16(float x, float y) {
    uint32_t r;
    asm("cvt.rn.bf16x2.f32 %0, %1, %2;" : "=r"(r) : "f"(y), "f"(x));
    return r;
}
__device__ __forceinline__ void split_bf16(float v, __nv_bfloat16& hi, __nv_bfloat16& lo) {
    hi = __float2bfloat16(v);
    lo = __float2bfloat16(v - __bfloat162float(hi));
}

// ---------------------------------------------------------------------------
// A-side split: src [M, K] fp32 -> dst [M, 3K] = [hi | lo | hi]
// ---------------------------------------------------------------------------
__global__ __launch_bounds__(256) void conv_a(const float* __restrict__ src,
                                              __nv_bfloat16* __restrict__ dst) {
    int idx = blockIdx.x * blockDim.x + threadIdx.x;
    const int K = DMODEL;
    if (idx >= MTOT * K / 4) return;
    int flat = idx * 4;
    int m = flat / K, k = flat % K;
    float4 v = *(const float4*)(src + flat);
    float vv[4] = {v.x, v.y, v.z, v.w};
    __nv_bfloat16 h[4], l[4];
#pragma unroll
    for (int j = 0; j < 4; j++) split_bf16(vv[j], h[j], l[j]);
    __nv_bfloat16* row = dst + (size_t)m * GK;
    *(uint2*)(row + k)         = *(uint2*)h;
    *(uint2*)(row + K + k)     = *(uint2*)l;
    *(uint2*)(row + 2 * K + k) = *(uint2*)h;
}

// B-side split: src [K, N] fp32 -> dst [N, 3K] = [hi | hi | lo] (transposed,
// optional scale folded in before splitting)
__global__ void conv_w(const float* __restrict__ src, __nv_bfloat16* __restrict__ dst,
                       int N, float scale) {
    __shared__ float tile[32][33];
    const int K = DMODEL;
    int k0 = blockIdx.y * 32, n0 = blockIdx.x * 32;
    int tx = threadIdx.x, ty = threadIdx.y;
#pragma unroll
    for (int i = 0; i < 32; i += 8)
        tile[ty + i][tx] = src[(size_t)(k0 + ty + i) * N + n0 + tx] * scale;
    __syncthreads();
#pragma unroll
    for (int i = 0; i < 32; i += 8) {
        int n = n0 + ty + i, k = k0 + tx;
        __nv_bfloat16 h, l;
        split_bf16(tile[tx][ty + i], h, l);
        __nv_bfloat16* row = dst + (size_t)n * GK;
        row[k]         = h;
        row[K + k]     = h;
        row[2 * K + k] = l;
    }
}

// ---------------------------------------------------------------------------
// bf16 mma.sync GEMM (proven in R3/R4)
// ---------------------------------------------------------------------------
#define BMt 128
#define BNt 128
#define BKt 32
#define PADt 40
#define NCHt (GK/BKt)

__global__ __launch_bounds__(256) void gemm_mma(const __nv_bfloat16* __restrict__ A,
                                                const __nv_bfloat16* __restrict__ Bt,
                                                float* __restrict__ C, int N) {
    __shared__ __nv_bfloat16 As[2][BMt * PADt];
    __shared__ __nv_bfloat16 Bs[2][BNt * PADt];

    int t = threadIdx.x, w = t >> 5, lane = t & 31;
    int m0 = blockIdx.y * BMt, n0 = blockIdx.x * BNt;
    int wm = (w >> 2) * 64;
    int wn = (w & 3) * 32;

    float acc[4][4][4];
#pragma unroll
    for (int i = 0; i < 4; i++)
#pragma unroll
        for (int j = 0; j < 4; j++)
#pragma unroll
            for (int r = 0; r < 4; r++) acc[i][j][r] = 0.f;

    uint32_t asb = smem_u32(As), bsb = smem_u32(Bs);

    int lrow0 = (t * 2) >> 2, lch0 = (t * 2) & 3;
    int lrow1 = (t * 2 + 1) >> 2, lch1 = (t * 2 + 1) & 3;

    const __nv_bfloat16* Ab = A  + (size_t)m0 * GK;
    const __nv_bfloat16* Bb = Bt + (size_t)n0 * GK;

    auto load_tile = [&](int kc, int buf) {
        uint32_t ab = asb + buf * (BMt * PADt * 2);
        uint32_t bb = bsb + buf * (BNt * PADt * 2);
        const __nv_bfloat16* Ak = Ab + kc * BKt;
        const __nv_bfloat16* Bk = Bb + kc * BKt;
        cp16(ab + (lrow0 * PADt + lch0 * 8) * 2, Ak + (size_t)lrow0 * GK + lch0 * 8);
        cp16(ab + (lrow1 * PADt + lch1 * 8) * 2, Ak + (size_t)lrow1 * GK + lch1 * 8);
        cp16(bb + (lrow0 * PADt + lch0 * 8) * 2, Bk + (size_t)lrow0 * GK + lch0 * 8);
        cp16(bb + (lrow1 * PADt + lch1 * 8) * 2, Bk + (size_t)lrow1 * GK + lch1 * 8);
        CP_COMMIT();
    };

    load_tile(0, 0);

    int li = lane >> 3;
    int lr = lane & 7;

    for (int kc = 0; kc < NCHt; kc++) {
        int buf = kc & 1;
        if (kc + 1 < NCHt) load_tile(kc + 1, buf ^ 1);
        if (kc + 1 < NCHt) { CP_WAIT(1); } else { CP_WAIT(0); }
        __syncthreads();

        uint32_t ab = asb + buf * (BMt * PADt * 2);
        uint32_t bb = bsb + buf * (BNt * PADt * 2);

#pragma unroll
        for (int ks = 0; ks < 2; ks++) {
            int k0 = ks * 16;
            uint32_t a[4][4];
#pragma unroll
            for (int mt = 0; mt < 4; mt++) {
                int row = wm + mt * 16 + (li & 1) * 8 + lr;
                int col = k0 + (li >> 1) * 8;
                ldsm4(a[mt][0], a[mt][1], a[mt][2], a[mt][3],
                      ab + (row * PADt + col) * 2);
            }
            uint32_t b[2][4];
#pragma unroll
            for (int p = 0; p < 2; p++) {
                int row = wn + p * 16 + (li >> 1) * 8 + lr;
                int col = k0 + (li & 1) * 8;
                ldsm4(b[p][0], b[p][1], b[p][2], b[p][3],
                      bb + (row * PADt + col) * 2);
            }
#pragma unroll
            for (int mt = 0; mt < 4; mt++)
#pragma unroll
                for (int nt = 0; nt < 4; nt++) {
                    int p = nt >> 1, off = (nt & 1) * 2;
                    mma16816(acc[mt][nt], a[mt][0], a[mt][1], a[mt][2], a[mt][3],
                             b[p][off], b[p][off + 1]);
                }
        }
        __syncthreads();
    }

    int cr = lane >> 2, cc = (lane & 3) * 2;
#pragma unroll
    for (int mt = 0; mt < 4; mt++)
#pragma unroll
        for (int nt = 0; nt < 4; nt++) {
            float* Cp = C + (size_t)(m0 + wm + mt * 16 + cr) * N + n0 + wn + nt * 8 + cc;
            *(float2*)Cp = make_float2(acc[mt][nt][0], acc[mt][nt][1]);
            *(float2*)(Cp + 8 * (size_t)N) = make_float2(acc[mt][nt][2], acc[mt][nt][3]);
        }
}

// ---------------------------------------------------------------------------
// finish_q: RoPE (scale already folded into wq) + split -> qb [b][h][s][192]
// ---------------------------------------------------------------------------
__global__ __launch_bounds__(256) void finish_q(const float* __restrict__ qkv,
                                                const float* __restrict__ cosT,
                                                const float* __restrict__ sinT,
                                                __nv_bfloat16* __restrict__ qb) {
    int idx = blockIdx.x * 256 + threadIdx.x;
    const int total = BATCH * SEQ * NH * 32;
    if (idx >= total) return;
    int j = idx & 31;
    int rest = idx >> 5;
    int h = rest % NH;
    int row = rest / NH;             // b*SEQ + s
    int s = row % SEQ, b = row / SEQ;

    const float* src = qkv + (size_t)row * NQKV + h * 64;
    float c  = cosT[s * 32 + j];
    float sn = sinT[s * 32 + j];
    float x1 = src[j], x2 = src[j + 32];
    float y1 = x1 * c - x2 * sn;
    float y2 = x2 * c + x1 * sn;

    __nv_bfloat16 h1, l1, h2, l2;
    split_bf16(y1, h1, l1);
    split_bf16(y2, h2, l2);
    __nv_bfloat16* d = qb + ((size_t)(b * NH + h) * SEQ + s) * 192;
    d[j]        = h1;  d[j + 32]  = h2;    // hi
    d[64 + j]   = l1;  d[96 + j]  = l2;    // lo
    d[128 + j]  = h1;  d[160 + j] = h2;    // hi
}

// finish_k: RoPE + fp32 new_k to d_out + split -> kb [b][kvh][s][hi|hi|lo]
__global__ __launch_bounds__(256) void finish_k(const float* __restrict__ qkv,
                                                const float* __restrict__ cosT,
                                                const float* __restrict__ sinT,
                                                float* __restrict__ kout,
                                                __nv_bfloat16* __restrict__ kb) {
    int idx = blockIdx.x * 256 + threadIdx.x;
    const int total = BATCH * SEQ * NKV * 32;
    if (idx >= total) return;
    int j = idx & 31;
    int rest = idx >> 5;
    int kvh = rest % NKV;
    int row = rest / NKV;
    int s = row % SEQ, b = row / SEQ;

    const float* src = qkv + (size_t)row * NQKV + 1024 + kvh * 64;
    float c  = cosT[s * 32 + j];
    float sn = sinT[s * 32 + j];
    float x1 = src[j], x2 = src[j + 32];
    float y1 = x1 * c - x2 * sn;
    float y2 = x2 * c + x1 * sn;

    float* ko = kout + ((size_t)row * NKV + kvh) * 64;
    ko[j] = y1;
    ko[j + 32] = y2;

    __nv_bfloat16 h1, l1, h2, l2;
    split_bf16(y1, h1, l1);
    split_bf16(y2, h2, l2);
    __nv_bfloat16* d = kb + ((size_t)(b * NKV + kvh) * SEQ + s) * 192;
    d[j]        = h1;  d[j + 32]  = h2;    // hi
    d[64 + j]   = h1;  d[96 + j]  = h2;    // hi
    d[128 + j]  = l1;  d[160 + j] = l2;    // lo
}

// finish_v: copy fp32 new_v to d_out + transposed hi/lo split
__global__ void finish_v(const float* __restrict__ qkv,
                         float* __restrict__ vout,
                         __nv_bfloat16* __restrict__ vhi,
                         __nv_bfloat16* __restrict__ vlo) {
    __shared__ float tile[32][33];
    int bkv = blockIdx.z;
    int b = bkv / NKV, kvh = bkv % NKV;
    int s0 = blockIdx.x * 32, d0 = blockIdx.y * 32;
    int tx = threadIdx.x, ty = threadIdx.y;          // 32 x 8
#pragma unroll
    for (int i = 0; i < 32; i += 8) {
        int s = s0 + ty + i;
        float v = qkv[((size_t)b * SEQ + s) * NQKV + 1280 + kvh * 64 + d0 + tx];
        tile[ty + i][tx] = v;
        vout[(((size_t)b * SEQ + s) * NKV + kvh) * 64 + d0 + tx] = v;
    }
    __syncthreads();
#pragma unroll
    for (int i = 0; i < 32; i += 8) {
        int d = d0 + ty + i, s = s0 + tx;
        __nv_bfloat16 h, l;
        split_bf16(tile[tx][ty + i], h, l);
        size_t off = ((size_t)bkv * HD + d) * SEQ + s;
        vhi[off] = h;
        vlo[off] = l;
    }
}

// ---------------------------------------------------------------------------
// Tensor-core flash attention, split-bf16. 64 q x (b,h) per CTA, 128 threads.
// V smem: [64 d][Vhi(64 keys) | Vlo(64 keys)].
// Epilogue writes split [hi|lo|hi] directly into the WO GEMM's A operand.
// ---------------------------------------------------------------------------
#define APAD 200
#define VPAD 136
#define ATTN2_SMEM ((2 * 64 * APAD + 64 * VPAD) * 2)

__global__ __launch_bounds__(128) void attn_mma(const __nv_bfloat16* __restrict__ Qb,
                                                const __nv_bfloat16* __restrict__ Kb,
                                                const __nv_bfloat16* __restrict__ Vhi,
                                                const __nv_bfloat16* __restrict__ Vlo,
                                                __nv_bfloat16* __restrict__ aoc) {
    extern __shared__ __nv_bfloat16 sb[];
    __nv_bfloat16* qs = sb;
    __nv_bfloat16* ks = sb + 64 * APAD;
    __nv_bfloat16* vs = sb + 2 * 64 * APAD;
    uint32_t qsa = smem_u32(qs), ksa = smem_u32(ks), vsa = smem_u32(vs);

    int t = threadIdx.x, w = t >> 5, lane = t & 31;
    int qt = blockIdx.x, h = blockIdx.y, b = blockIdx.z;
    int kvh = h >> 2;
    int li = lane >> 3, lr = lane & 7;
    int r0 = lane >> 2;
    int cc = (lane & 3) * 2;

    const __nv_bfloat16* qsrc = Qb + ((size_t)(b * NH + h) * SEQ + (size_t)qt * 64) * 192;
#pragma unroll
    for (int i = 0; i < 12; i++) {
        int c = t + 128 * i;
        int row = c / 24, seg = c % 24;
        cp16(qsa + (row * APAD + seg * 8) * 2, qsrc + (size_t)row * 192 + seg * 8);
    }
    CP_COMMIT();

    float m0 = -1e30f, m1 = -1e30f, l0 = 0.f, l1 = 0.f;
    float of[8][4];
#pragma unroll
    for (int j = 0; j < 8; j++)
#pragma unroll
        for (int e = 0; e < 4; e++) of[j][e] = 0.f;

    const __nv_bfloat16* ksrc0 = Kb + (size_t)(b * NKV + kvh) * SEQ * 192;
    const __nv_bfloat16* vh0 = Vhi + (size_t)(b * NKV + kvh) * HD * SEQ;
    const __nv_bfloat16* vl0 = Vlo + (size_t)(b * NKV + kvh) * HD * SEQ;

    for (int kt = 0; kt <= qt; kt++) {
        const __nv_bfloat16* ksrc = ksrc0 + (size_t)kt * 64 * 192;
#pragma unroll
        for (int i = 0; i < 12; i++) {
            int c = t + 128 * i;
            int row = c / 24, seg = c % 24;
            cp16(ksa + (row * APAD + seg * 8) * 2, ksrc + (size_t)row * 192 + seg * 8);
        }
        // V tile: [64 d][128] = [Vhi keys | Vlo keys]
#pragma unroll
        for (int i = 0; i < 8; i++) {
            int c = t + 128 * i;
            int d = c >> 4, seg = c & 15;
            const __nv_bfloat16* src = (seg < 8 ? vh0 : vl0)
                                       + (size_t)d * SEQ + kt * 64 + (seg & 7) * 8;
            cp16(vsa + (d * VPAD + seg * 8) * 2, src);
        }
        CP_COMMIT();
        CP_WAIT(0);
        __syncthreads();

        // ---- S = Q' K'^T ----
        float sf[8][4];
#pragma unroll
        for (int j = 0; j < 8; j++)
#pragma unroll
            for (int e = 0; e < 4; e++) sf[j][e] = 0.f;
#pragma unroll
        for (int ks12 = 0; ks12 < 12; ks12++) {
            int k0 = ks12 * 16;
            uint32_t a0, a1, a2, a3;
            ldsm4(a0, a1, a2, a3,
                  qsa + ((w * 16 + (li & 1) * 8 + lr) * APAD + k0 + (li >> 1) * 8) * 2);
#pragma unroll
            for (int p = 0; p < 4; p++) {
                uint32_t b0, b1, b2, b3;
                ldsm4(b0, b1, b2, b3,
                      ksa + ((p * 16 + (li >> 1) * 8 + lr) * APAD + k0 + (li & 1) * 8) * 2);
                mma16816(sf[2 * p],     a0, a1, a2, a3, b0, b1);
                mma16816(sf[2 * p + 1], a0, a1, a2, a3, b2, b3);
            }
        }

        if (kt == qt) {
            int q0 = w * 16 + r0, q1 = q0 + 8;
#pragma unroll
            for (int j = 0; j < 8; j++) {
                int key = 8 * j + cc;
                if (key     > q0) sf[j][0] = -1e30f;
                if (key + 1 > q0) sf[j][1] = -1e30f;
                if (key     > q1) sf[j][2] = -1e30f;
                if (key + 1 > q1) sf[j][3] = -1e30f;
            }
        }

        // ---- online softmax ----
        float mx0 = -1e30f, mx1 = -1e30f;
#pragma unroll
        for (int j = 0; j < 8; j++) {
            mx0 = fmaxf(mx0, fmaxf(sf[j][0], sf[j][1]));
            mx1 = fmaxf(mx1, fmaxf(sf[j][2], sf[j][3]));
        }
        mx0 = fmaxf(mx0, __shfl_xor_sync(0xffffffffu, mx0, 1));
        mx0 = fmaxf(mx0, __shfl_xor_sync(0xffffffffu, mx0, 2));
        mx1 = fmaxf(mx1, __shfl_xor_sync(0xffffffffu, mx1, 1));
        mx1 = fmaxf(mx1, __shfl_xor_sync(0xffffffffu, mx1, 2));
        float nm0 = fmaxf(m0, mx0), nm1 = fmaxf(m1, mx1);
        float al0 = __expf(m0 - nm0), al1 = __expf(m1 - nm1);
        m0 = nm0; m1 = nm1;

        float s0 = 0.f, s1 = 0.f;
#pragma unroll
        for (int j = 0; j < 8; j++) {
            sf[j][0] = __expf(sf[j][0] - m0); s0 += sf[j][0];
            sf[j][1] = __expf(sf[j][1] - m0); s0 += sf[j][1];
            sf[j][2] = __expf(sf[j][2] - m1); s1 += sf[j][2];
            sf[j][3] = __expf(sf[j][3] - m1); s1 += sf[j][3];
        }
        s0 += __shfl_xor_sync(0xffffffffu, s0, 1);
        s0 += __shfl_xor_sync(0xffffffffu, s0, 2);
        s1 += __shfl_xor_sync(0xffffffffu, s1, 1);
        s1 += __shfl_xor_sync(0xffffffffu, s1, 2);
        l0 = l0 * al0 + s0;
        l1 = l1 * al1 + s1;

#pragma unroll
        for (int j = 0; j < 8; j++) {
            of[j][0] *= al0; of[j][1] *= al0;
            of[j][2] *= al1; of[j][3] *= al1;
        }

        // ---- split P into bf16 A-fragments ----
        uint32_t ah[4][4], alf[4][4];
#pragma unroll
        for (int kk = 0; kk < 4; kk++) {
            float c00 = sf[2 * kk][0], c01 = sf[2 * kk][1];
            float c02 = sf[2 * kk][2], c03 = sf[2 * kk][3];
            float c10 = sf[2 * kk + 1][0], c11 = sf[2 * kk + 1][1];
            float c12 = sf[2 * kk + 1][2], c13 = sf[2 * kk + 1][3];
            uint32_t h0 = pack_bf16(c00, c01), h1 = pack_bf16(c02, c03);
            uint32_t h2 = pack_bf16(c10, c11), h3 = pack_bf16(c12, c13);
            ah[kk][0] = h0; ah[kk][1] = h1; ah[kk][2] = h2; ah[kk][3] = h3;
            __nv_bfloat162 b0 = *(__nv_bfloat162*)&h0;
            __nv_bfloat162 b1 = *(__nv_bfloat162*)&h1;
            __nv_bfloat162 b2 = *(__nv_bfloat162*)&h2;
            __nv_bfloat162 b3 = *(__nv_bfloat162*)&h3;
            alf[kk][0] = pack_bf16(c00 - __bfloat162float(b0.x), c01 - __bfloat162float(b0.y));
            alf[kk][1] = pack_bf16(c02 - __bfloat162float(b1.x), c03 - __bfloat162float(b1.y));
            alf[kk][2] = pack_bf16(c10 - __bfloat162float(b2.x), c11 - __bfloat162float(b2.y));
            alf[kk][3] = pack_bf16(c12 - __bfloat162float(b3.x), c13 - __bfloat162float(b3.y));
        }

        // ---- O += P' V': Phi*Vhi, Plo*Vhi, Phi*Vlo ----
#pragma unroll
        for (int ks12 = 0; ks12 < 12; ks12++) {
            int kk = ks12 & 3, sel = ks12 >> 2;
            uint32_t* A = (sel == 1) ? alf[kk] : ah[kk];
            int k0 = (sel == 2 ? 64 : 0) + kk * 16;
#pragma unroll
            for (int p = 0; p < 4; p++) {
                uint32_t b0, b1, b2, b3;
                ldsm4(b0, b1, b2, b3,
                      vsa + ((p * 16 + (li >> 1) * 8 + lr) * VPAD + k0 + (li & 1) * 8) * 2);
                mma16816(of[2 * p],     A[0], A[1], A[2], A[3], b0, b1);
                mma16816(of[2 * p + 1], A[0], A[1], A[2], A[3], b2, b3);
            }
        }
        __syncthreads();
    }

    // ---- epilogue: write split [hi|lo|hi] directly into aoc ----
    float inv0 = 1.f / l0, inv1 = 1.f / l1;
    int row0 = b * SEQ + qt * 64 + w * 16 + r0;
    int row1 = row0 + 8;
#pragma unroll
    for (int j = 0; j < 8; j++) {
        int colq = h * 64 + 8 * j + cc;
        {
            float v0 = of[j][0] * inv0, v1 = of[j][1] * inv0;
            uint32_t hp = pack_bf16(v0, v1);
            __nv_bfloat162 hb = *(__nv_bfloat162*)&hp;
            uint32_t lp = pack_bf16(v0 - __bfloat162float(hb.x), v1 - __bfloat162float(hb.y));
            uint32_t* base = (uint32_t*)(aoc + (size_t)row0 * GK + colq);
            base[0]              = hp;
            *(uint32_t*)((char*)base + 1024 * 2) = lp;
            *(uint32_t*)((char*)base + 2048 * 2) = hp;
        }
        {
            float v0 = of[j][2] * inv1, v1 = of[j][3] * inv1;
            uint32_t hp = pack_bf16(v0, v1);
            __nv_bfloat162 hb = *(__nv_bfloat162*)&hp;
            uint32_t lp = pack_bf16(v0 - __bfloat162float(hb.x), v1 - __bfloat162float(hb.y));
            uint32_t* base = (uint32_t*)(aoc + (size_t)row1 * GK + colq);
            base[0]              = hp;
            *(uint32_t*)((char*)base + 1024 * 2) = lp;
            *(uint32_t*)((char*)base + 2048 * 2) = hp;
        }
    }
}

// ---------------------------------------------------------------------------
extern "C" void kernel_launch(void* const* d_in, const int* in_sizes, int n_in,
                              void* d_out, int out_size) {
    const float* x    = (const float*)d_in[0];
    const float* cosT = (const float*)d_in[1];
    const float* sinT = (const float*)d_in[2];
    // d_in[3] = mask: unused (hard causal mask identical in fp32)
    const float* wq   = (const float*)d_in[4];
    const float* wk   = (const float*)d_in[5];
    const float* wv   = (const float*)d_in[6];
    const float* wo   = (const float*)d_in[7];

    float* out  = (float*)d_out;
    float* kout = out + OUT_ELEMS;
    float* vout = out + OUT_ELEMS + KV_ELEMS;

    float* qkv;
    __nv_bfloat16 *xc, *aoc, *wqkvt, *wot, *qb, *kb, *vhi, *vlo;
    cudaGetSymbolAddress((void**)&qkv, g_qkv);
    cudaGetSymbolAddress((void**)&xc,  g_xc);
    cudaGetSymbolAddress((void**)&aoc, g_aoc);
    cudaGetSymbolAddress((void**)&wqkvt, g_wqkvt);
    cudaGetSymbolAddress((void**)&wot, g_wot);
    cudaGetSymbolAddress((void**)&qb,  g_qb);
    cudaGetSymbolAddress((void**)&kb,  g_kb);
    cudaGetSymbolAddress((void**)&vhi, g_vhi);
    cudaGetSymbolAddress((void**)&vlo, g_vlo);

    cudaFuncSetAttribute(attn_mma, cudaFuncAttributeMaxDynamicSharedMemorySize, ATTN2_SMEM);

    // Split conversions (0.125 q-scale folded into wq)
    conv_a<<<(MTOT * DMODEL / 4 + 255) / 256, 256>>>(x, xc);
    dim3 wb(32, 8);
    conv_w<<<dim3((NH * HD) / 32, DMODEL / 32), wb>>>(wq, wqkvt, NH * HD, 0.125f);
    conv_w<<<dim3((NKV * HD) / 32, DMODEL / 32), wb>>>(wk, wqkvt + (size_t)1024 * GK, NKV * HD, 1.f);
    conv_w<<<dim3((NKV * HD) / 32, DMODEL / 32), wb>>>(wv, wqkvt + (size_t)1280 * GK, NKV * HD, 1.f);
    conv_w<<<dim3(DMODEL / 32, DMODEL / 32), wb>>>(wo, wot, DMODEL, 1.f);

    // Fused QKV projection (one full-occupancy launch)
    gemm_mma<<<dim3(NQKV / 128, MTOT / 128), 256>>>(xc, wqkvt, qkv, NQKV);

    // RoPE + split + fp32 kv-cache outputs
    finish_q<<<(BATCH * SEQ * NH * 32 + 255) / 256, 256>>>(qkv, cosT, sinT, qb);
    finish_k<<<(BATCH * SEQ * NKV * 32 + 255) / 256, 256>>>(qkv, cosT, sinT, kout, kb);
    finish_v<<<dim3(SEQ / 32, HD / 32, BATCH * NKV), dim3(32, 8)>>>(qkv, vout, vhi, vlo);

    // Tensor-core flash attention (writes split A operand for WO directly)
    attn_mma<<<dim3(SEQ / 64, NH, BATCH), 128, ATTN2_SMEM>>>(qb, kb, vhi, vlo, aoc);

    // Output projection
    gemm_mma<<<dim3(DMODEL / 128, MTOT / 128), 256>>>(aoc, wot, out, DMODEL);
}

// round 6
// speedup vs baseline: 2.3795x; 1.0355x over previous
#include <cuda_runtime.h>
#include <cuda_bf16.h>
#include <cstdint>

// Problem constants
#define BATCH 2
#define SEQ 2048
#define DMODEL 1024
#define NH 16
#define NKV 4
#define HD 64
#define OUT_ELEMS  (BATCH*SEQ*DMODEL)
#define KV_ELEMS   (BATCH*SEQ*NKV*HD)

#define MTOT (BATCH*SEQ)        // 4096
#define GK   (3*DMODEL)         // 3072 split-K (hi|lo|hi vs hi|hi|lo)
#define NQKV 1536               // fused QKV output width

// ---------------------------------------------------------------------------
// Scratch (device globals; no runtime allocation allowed)
// ---------------------------------------------------------------------------
__device__ float g_qkv[MTOT*NQKV];                   // fused QKV gemm output
__device__ __nv_bfloat16 g_xc   [MTOT*GK];           // x split [M, 3K]
__device__ __nv_bfloat16 g_aoc  [MTOT*GK];           // attn out split [M, 3K]
__device__ __nv_bfloat16 g_wqkvt[NQKV*GK];           // [wq|wk|wv]^T split
__device__ __nv_bfloat16 g_wot  [DMODEL*GK];
// Attention operands (pre-split bf16)
__device__ __nv_bfloat16 g_qb [BATCH*NH*SEQ*192];    // [b][h][s][hi|lo|hi]
__device__ __nv_bfloat16 g_kb [BATCH*NKV*SEQ*192];   // [b][kvh][s][hi|hi|lo]
__device__ __nv_bfloat16 g_vhi[BATCH*NKV*HD*SEQ];    // [b][kvh][d][s] transposed
__device__ __nv_bfloat16 g_vlo[BATCH*NKV*HD*SEQ];

// ---------------------------------------------------------------------------
// Baseline-PTX helpers
// ---------------------------------------------------------------------------
__device__ __forceinline__ uint32_t smem_u32(const void* p) {
    uint32_t a;
    asm("{ .reg .u64 t; cvta.to.shared.u64 t, %1; cvt.u32.u64 %0, t; }" : "=r"(a) : "l"(p));
    return a;
}
__device__ __forceinline__ void cp16(uint32_t saddr, const void* g) {
    asm volatile("cp.async.cg.shared.global [%0], [%1], 16;" :: "r"(saddr), "l"(g) : "memory");
}
#define CP_COMMIT() asm volatile("cp.async.commit_group;" ::: "memory")
#define CP_WAIT(n)  asm volatile("cp.async.wait_group %0;" :: "n"(n) : "memory")

__device__ __forceinline__ void ldsm4(uint32_t& r0, uint32_t& r1, uint32_t& r2, uint32_t& r3,
                                      uint32_t a) {
    asm volatile("ldmatrix.sync.aligned.m8n8.x4.shared.b16 {%0,%1,%2,%3}, [%4];"
                 : "=r"(r0), "=r"(r1), "=r"(r2), "=r"(r3) : "r"(a));
}
__device__ __forceinline__ void mma16816(float* c, uint32_t a0, uint32_t a1, uint32_t a2,
                                         uint32_t a3, uint32_t b0, uint32_t b1) {
    asm volatile(
        "mma.sync.aligned.m16n8k16.row.col.f32.bf16.bf16.f32 "
        "{%0,%1,%2,%3},{%4,%5,%6,%7},{%8,%9},{%0,%1,%2,%3};"
        : "+f"(c[0]), "+f"(c[1]), "+f"(c[2]), "+f"(c[3])
        : "r"(a0), "r"(a1), "r"(a2), "r"(a3), "r"(b0), "r"(b1));
}
__device__ __forceinline__ uint32_t pack_bf16(float x, float y) {
    uint32_t r;
    asm("cvt.rn.bf16x2.f32 %0, %1, %2;" : "=r"(r) : "f"(y), "f"(x));
    return r;
}
__device__ __forceinline__ void split_bf16(float v, __nv_bfloat16& hi, __nv_bfloat16& lo) {
    hi = __float2bfloat16(v);
    lo = __float2bfloat16(v - __bfloat162float(hi));
}

// ---------------------------------------------------------------------------
// A-side split: src [M, K] fp32 -> dst [M, 3K] = [hi | lo | hi]
// ---------------------------------------------------------------------------
__global__ __launch_bounds__(256) void conv_a(const float* __restrict__ src,
                                              __nv_bfloat16* __restrict__ dst) {
    int idx = blockIdx.x * blockDim.x + threadIdx.x;
    const int K = DMODEL;
    if (idx >= MTOT * K / 4) return;
    int flat = idx * 4;
    int m = flat / K, k = flat % K;
    float4 v = *(const float4*)(src + flat);
    float vv[4] = {v.x, v.y, v.z, v.w};
    __nv_bfloat16 h[4], l[4];
#pragma unroll
    for (int j = 0; j < 4; j++) split_bf16(vv[j], h[j], l[j]);
    __nv_bfloat16* row = dst + (size_t)m * GK;
    *(uint2*)(row + k)         = *(uint2*)h;
    *(uint2*)(row + K + k)     = *(uint2*)l;
    *(uint2*)(row + 2 * K + k) = *(uint2*)h;
}

// Fused weight split for [wq|wk|wv] -> wqkvt [1536, 3K] (boundaries 32-aligned)
__global__ void conv_qkv(const float* __restrict__ wq, const float* __restrict__ wk,
                         const float* __restrict__ wv, __nv_bfloat16* __restrict__ dst) {
    __shared__ float tile[32][33];
    const int K = DMODEL;
    int k0 = blockIdx.y * 32, n0 = blockIdx.x * 32;
    const float* src;
    int nloc, N;
    float scale = 1.f;
    if (n0 < 1024)      { src = wq; nloc = n0;        N = 1024; scale = 0.125f; }
    else if (n0 < 1280) { src = wk; nloc = n0 - 1024; N = 256; }
    else                { src = wv; nloc = n0 - 1280; N = 256; }
    int tx = threadIdx.x, ty = threadIdx.y;
#pragma unroll
    for (int i = 0; i < 32; i += 8)
        tile[ty + i][tx] = src[(size_t)(k0 + ty + i) * N + nloc + tx] * scale;
    __syncthreads();
#pragma unroll
    for (int i = 0; i < 32; i += 8) {
        int n = n0 + ty + i, k = k0 + tx;
        __nv_bfloat16 h, l;
        split_bf16(tile[tx][ty + i], h, l);
        __nv_bfloat16* row = dst + (size_t)n * GK;
        row[k]         = h;
        row[K + k]     = h;
        row[2 * K + k] = l;
    }
}

// B-side split for wo
__global__ void conv_w(const float* __restrict__ src, __nv_bfloat16* __restrict__ dst,
                       int N) {
    __shared__ float tile[32][33];
    const int K = DMODEL;
    int k0 = blockIdx.y * 32, n0 = blockIdx.x * 32;
    int tx = threadIdx.x, ty = threadIdx.y;
#pragma unroll
    for (int i = 0; i < 32; i += 8)
        tile[ty + i][tx] = src[(size_t)(k0 + ty + i) * N + n0 + tx];
    __syncthreads();
#pragma unroll
    for (int i = 0; i < 32; i += 8) {
        int n = n0 + ty + i, k = k0 + tx;
        __nv_bfloat16 h, l;
        split_bf16(tile[tx][ty + i], h, l);
        __nv_bfloat16* row = dst + (size_t)n * GK;
        row[k]         = h;
        row[K + k]     = h;
        row[2 * K + k] = l;
    }
}

// ---------------------------------------------------------------------------
// bf16 mma.sync GEMM, 4-stage cp.async pipeline, one barrier per K-chunk.
// ---------------------------------------------------------------------------
#define BMt 128
#define BNt 128
#define BKt 32
#define PADt 40
#define NCHt (GK/BKt)           // 96
#define STAGES 4
#define STAGE_ELEMS ((BMt + BNt) * PADt)        // 10240 bf16
#define GEMM_SMEM (STAGES * STAGE_ELEMS * 2)    // 81920 B

__global__ __launch_bounds__(256) void gemm_mma(const __nv_bfloat16* __restrict__ A,
                                                const __nv_bfloat16* __restrict__ Bt,
                                                float* __restrict__ C, int N) {
    extern __shared__ __nv_bfloat16 gsm[];
    uint32_t smb = smem_u32(gsm);

    int t = threadIdx.x, w = t >> 5, lane = t & 31;
    int m0 = blockIdx.y * BMt, n0 = blockIdx.x * BNt;
    int wm = (w >> 2) * 64;
    int wn = (w & 3) * 32;

    float acc[4][4][4];
#pragma unroll
    for (int i = 0; i < 4; i++)
#pragma unroll
        for (int j = 0; j < 4; j++)
#pragma unroll
            for (int r = 0; r < 4; r++) acc[i][j][r] = 0.f;

    int lrow0 = (t * 2) >> 2, lch0 = (t * 2) & 3;
    int lrow1 = (t * 2 + 1) >> 2, lch1 = (t * 2 + 1) & 3;

    const __nv_bfloat16* Ab = A  + (size_t)m0 * GK;
    const __nv_bfloat16* Bb = Bt + (size_t)n0 * GK;

    auto load_tile = [&](int kc, int s) {
        if (kc < NCHt) {
            uint32_t ab = smb + s * (STAGE_ELEMS * 2);
            uint32_t bb = ab + BMt * PADt * 2;
            const __nv_bfloat16* Ak = Ab + kc * BKt;
            const __nv_bfloat16* Bk = Bb + kc * BKt;
            cp16(ab + (lrow0 * PADt + lch0 * 8) * 2, Ak + (size_t)lrow0 * GK + lch0 * 8);
            cp16(ab + (lrow1 * PADt + lch1 * 8) * 2, Ak + (size_t)lrow1 * GK + lch1 * 8);
            cp16(bb + (lrow0 * PADt + lch0 * 8) * 2, Bk + (size_t)lrow0 * GK + lch0 * 8);
            cp16(bb + (lrow1 * PADt + lch1 * 8) * 2, Bk + (size_t)lrow1 * GK + lch1 * 8);
        }
        CP_COMMIT();   // empty groups at the tail keep wait-group accounting exact
    };

#pragma unroll
    for (int s = 0; s < STAGES - 1; s++) load_tile(s, s);

    int li = lane >> 3;
    int lr = lane & 7;

    for (int kc = 0; kc < NCHt; kc++) {
        CP_WAIT(STAGES - 2);
        __syncthreads();
        load_tile(kc + STAGES - 1, (kc + STAGES - 1) % STAGES);

        int s = kc % STAGES;
        uint32_t ab = smb + s * (STAGE_ELEMS * 2);
        uint32_t bb = ab + BMt * PADt * 2;

#pragma unroll
        for (int ks = 0; ks < 2; ks++) {
            int k0 = ks * 16;
            uint32_t a[4][4];
#pragma unroll
            for (int mt = 0; mt < 4; mt++) {
                int row = wm + mt * 16 + (li & 1) * 8 + lr;
                int col = k0 + (li >> 1) * 8;
                ldsm4(a[mt][0], a[mt][1], a[mt][2], a[mt][3],
                      ab + (row * PADt + col) * 2);
            }
            uint32_t b[2][4];
#pragma unroll
            for (int p = 0; p < 2; p++) {
                int row = wn + p * 16 + (li >> 1) * 8 + lr;
                int col = k0 + (li & 1) * 8;
                ldsm4(b[p][0], b[p][1], b[p][2], b[p][3],
                      bb + (row * PADt + col) * 2);
            }
#pragma unroll
            for (int mt = 0; mt < 4; mt++)
#pragma unroll
                for (int nt = 0; nt < 4; nt++) {
                    int p = nt >> 1, off = (nt & 1) * 2;
                    mma16816(acc[mt][nt], a[mt][0], a[mt][1], a[mt][2], a[mt][3],
                             b[p][off], b[p][off + 1]);
                }
        }
    }

    int cr = lane >> 2, cc = (lane & 3) * 2;
#pragma unroll
    for (int mt = 0; mt < 4; mt++)
#pragma unroll
        for (int nt = 0; nt < 4; nt++) {
            float* Cp = C + (size_t)(m0 + wm + mt * 16 + cr) * N + n0 + wn + nt * 8 + cc;
            *(float2*)Cp = make_float2(acc[mt][nt][0], acc[mt][nt][1]);
            *(float2*)(Cp + 8 * (size_t)N) = make_float2(acc[mt][nt][2], acc[mt][nt][3]);
        }
}

// ---------------------------------------------------------------------------
// finish_q / finish_k / finish_v (unchanged from R5)
// ---------------------------------------------------------------------------
__global__ __launch_bounds__(256) void finish_q(const float* __restrict__ qkv,
                                                const float* __restrict__ cosT,
                                                const float* __restrict__ sinT,
                                                __nv_bfloat16* __restrict__ qb) {
    int idx = blockIdx.x * 256 + threadIdx.x;
    const int total = BATCH * SEQ * NH * 32;
    if (idx >= total) return;
    int j = idx & 31;
    int rest = idx >> 5;
    int h = rest % NH;
    int row = rest / NH;
    int s = row % SEQ, b = row / SEQ;

    const float* src = qkv + (size_t)row * NQKV + h * 64;
    float c  = cosT[s * 32 + j];
    float sn = sinT[s * 32 + j];
    float x1 = src[j], x2 = src[j + 32];
    float y1 = x1 * c - x2 * sn;
    float y2 = x2 * c + x1 * sn;

    __nv_bfloat16 h1, l1, h2, l2;
    split_bf16(y1, h1, l1);
    split_bf16(y2, h2, l2);
    __nv_bfloat16* d = qb + ((size_t)(b * NH + h) * SEQ + s) * 192;
    d[j]        = h1;  d[j + 32]  = h2;
    d[64 + j]   = l1;  d[96 + j]  = l2;
    d[128 + j]  = h1;  d[160 + j] = h2;
}

__global__ __launch_bounds__(256) void finish_k(const float* __restrict__ qkv,
                                                const float* __restrict__ cosT,
                                                const float* __restrict__ sinT,
                                                float* __restrict__ kout,
                                                __nv_bfloat16* __restrict__ kb) {
    int idx = blockIdx.x * 256 + threadIdx.x;
    const int total = BATCH * SEQ * NKV * 32;
    if (idx >= total) return;
    int j = idx & 31;
    int rest = idx >> 5;
    int kvh = rest % NKV;
    int row = rest / NKV;
    int s = row % SEQ, b = row / SEQ;

    const float* src = qkv + (size_t)row * NQKV + 1024 + kvh * 64;
    float c  = cosT[s * 32 + j];
    float sn = sinT[s * 32 + j];
    float x1 = src[j], x2 = src[j + 32];
    float y1 = x1 * c - x2 * sn;
    float y2 = x2 * c + x1 * sn;

    float* ko = kout + ((size_t)row * NKV + kvh) * 64;
    ko[j] = y1;
    ko[j + 32] = y2;

    __nv_bfloat16 h1, l1, h2, l2;
    split_bf16(y1, h1, l1);
    split_bf16(y2, h2, l2);
    __nv_bfloat16* d = kb + ((size_t)(b * NKV + kvh) * SEQ + s) * 192;
    d[j]        = h1;  d[j + 32]  = h2;
    d[64 + j]   = h1;  d[96 + j]  = h2;
    d[128 + j]  = l1;  d[160 + j] = l2;
}

__global__ void finish_v(const float* __restrict__ qkv,
                         float* __restrict__ vout,
                         __nv_bfloat16* __restrict__ vhi,
                         __nv_bfloat16* __restrict__ vlo) {
    __shared__ float tile[32][33];
    int bkv = blockIdx.z;
    int b = bkv / NKV, kvh = bkv % NKV;
    int s0 = blockIdx.x * 32, d0 = blockIdx.y * 32;
    int tx = threadIdx.x, ty = threadIdx.y;
#pragma unroll
    for (int i = 0; i < 32; i += 8) {
        int s = s0 + ty + i;
        float v = qkv[((size_t)b * SEQ + s) * NQKV + 1280 + kvh * 64 + d0 + tx];
        tile[ty + i][tx] = v;
        vout[(((size_t)b * SEQ + s) * NKV + kvh) * 64 + d0 + tx] = v;
    }
    __syncthreads();
#pragma unroll
    for (int i = 0; i < 32; i += 8) {
        int d = d0 + ty + i, s = s0 + tx;
        __nv_bfloat16 h, l;
        split_bf16(tile[tx][ty + i], h, l);
        size_t off = ((size_t)bkv * HD + d) * SEQ + s;
        vhi[off] = h;
        vlo[off] = l;
    }
}

// ---------------------------------------------------------------------------
// Tensor-core flash attention, split-bf16 + split K/V wait groups.
// ---------------------------------------------------------------------------
#define APAD 200
#define VPAD 136
#define ATTN2_SMEM ((2 * 64 * APAD + 64 * VPAD) * 2)

__global__ __launch_bounds__(128) void attn_mma(const __nv_bfloat16* __restrict__ Qb,
                                                const __nv_bfloat16* __restrict__ Kb,
                                                const __nv_bfloat16* __restrict__ Vhi,
                                                const __nv_bfloat16* __restrict__ Vlo,
                                                __nv_bfloat16* __restrict__ aoc) {
    extern __shared__ __nv_bfloat16 sb[];
    __nv_bfloat16* qs = sb;
    __nv_bfloat16* ks = sb + 64 * APAD;
    __nv_bfloat16* vs = sb + 2 * 64 * APAD;
    uint32_t qsa = smem_u32(qs), ksa = smem_u32(ks), vsa = smem_u32(vs);

    int t = threadIdx.x, w = t >> 5, lane = t & 31;
    int qt = blockIdx.x, h = blockIdx.y, b = blockIdx.z;
    int kvh = h >> 2;
    int li = lane >> 3, lr = lane & 7;
    int r0 = lane >> 2;
    int cc = (lane & 3) * 2;

    const __nv_bfloat16* qsrc = Qb + ((size_t)(b * NH + h) * SEQ + (size_t)qt * 64) * 192;
#pragma unroll
    for (int i = 0; i < 12; i++) {
        int c = t + 128 * i;
        int row = c / 24, seg = c % 24;
        cp16(qsa + (row * APAD + seg * 8) * 2, qsrc + (size_t)row * 192 + seg * 8);
    }
    CP_COMMIT();

    float m0 = -1e30f, m1 = -1e30f, l0 = 0.f, l1 = 0.f;
    float of[8][4];
#pragma unroll
    for (int j = 0; j < 8; j++)
#pragma unroll
        for (int e = 0; e < 4; e++) of[j][e] = 0.f;

    const __nv_bfloat16* ksrc0 = Kb + (size_t)(b * NKV + kvh) * SEQ * 192;
    const __nv_bfloat16* vh0 = Vhi + (size_t)(b * NKV + kvh) * HD * SEQ;
    const __nv_bfloat16* vl0 = Vlo + (size_t)(b * NKV + kvh) * HD * SEQ;

    for (int kt = 0; kt <= qt; kt++) {
        // K tile (own commit group)
        const __nv_bfloat16* ksrc = ksrc0 + (size_t)kt * 64 * 192;
#pragma unroll
        for (int i = 0; i < 12; i++) {
            int c = t + 128 * i;
            int row = c / 24, seg = c % 24;
            cp16(ksa + (row * APAD + seg * 8) * 2, ksrc + (size_t)row * 192 + seg * 8);
        }
        CP_COMMIT();
        // V tile (own commit group, streams in during S-compute)
#pragma unroll
        for (int i = 0; i < 8; i++) {
            int c = t + 128 * i;
            int d = c >> 4, seg = c & 15;
            const __nv_bfloat16* src = (seg < 8 ? vh0 : vl0)
                                       + (size_t)d * SEQ + kt * 64 + (seg & 7) * 8;
            cp16(vsa + (d * VPAD + seg * 8) * 2, src);
        }
        CP_COMMIT();

        CP_WAIT(1);          // Q(+prior groups) and K done; V may be in flight
        __syncthreads();

        // ---- S = Q' K'^T ----
        float sf[8][4];
#pragma unroll
        for (int j = 0; j < 8; j++)
#pragma unroll
            for (int e = 0; e < 4; e++) sf[j][e] = 0.f;
#pragma unroll
        for (int ks12 = 0; ks12 < 12; ks12++) {
            int k0 = ks12 * 16;
            uint32_t a0, a1, a2, a3;
            ldsm4(a0, a1, a2, a3,
                  qsa + ((w * 16 + (li & 1) * 8 + lr) * APAD + k0 + (li >> 1) * 8) * 2);
#pragma unroll
            for (int p = 0; p < 4; p++) {
                uint32_t b0, b1, b2, b3;
                ldsm4(b0, b1, b2, b3,
                      ksa + ((p * 16 + (li >> 1) * 8 + lr) * APAD + k0 + (li & 1) * 8) * 2);
                mma16816(sf[2 * p],     a0, a1, a2, a3, b0, b1);
                mma16816(sf[2 * p + 1], a0, a1, a2, a3, b2, b3);
            }
        }

        if (kt == qt) {
            int q0 = w * 16 + r0, q1 = q0 + 8;
#pragma unroll
            for (int j = 0; j < 8; j++) {
                int key = 8 * j + cc;
                if (key     > q0) sf[j][0] = -1e30f;
                if (key + 1 > q0) sf[j][1] = -1e30f;
                if (key     > q1) sf[j][2] = -1e30f;
                if (key + 1 > q1) sf[j][3] = -1e30f;
            }
        }

        // ---- online softmax ----
        float mx0 = -1e30f, mx1 = -1e30f;
#pragma unroll
        for (int j = 0; j < 8; j++) {
            mx0 = fmaxf(mx0, fmaxf(sf[j][0], sf[j][1]));
            mx1 = fmaxf(mx1, fmaxf(sf[j][2], sf[j][3]));
        }
        mx0 = fmaxf(mx0, __shfl_xor_sync(0xffffffffu, mx0, 1));
        mx0 = fmaxf(mx0, __shfl_xor_sync(0xffffffffu, mx0, 2));
        mx1 = fmaxf(mx1, __shfl_xor_sync(0xffffffffu, mx1, 1));
        mx1 = fmaxf(mx1, __shfl_xor_sync(0xffffffffu, mx1, 2));
        float nm0 = fmaxf(m0, mx0), nm1 = fmaxf(m1, mx1);
        float al0 = __expf(m0 - nm0), al1 = __expf(m1 - nm1);
        m0 = nm0; m1 = nm1;

        float s0 = 0.f, s1 = 0.f;
#pragma unroll
        for (int j = 0; j < 8; j++) {
            sf[j][0] = __expf(sf[j][0] - m0); s0 += sf[j][0];
            sf[j][1] = __expf(sf[j][1] - m0); s0 += sf[j][1];
            sf[j][2] = __expf(sf[j][2] - m1); s1 += sf[j][2];
            sf[j][3] = __expf(sf[j][3] - m1); s1 += sf[j][3];
        }
        s0 += __shfl_xor_sync(0xffffffffu, s0, 1);
        s0 += __shfl_xor_sync(0xffffffffu, s0, 2);
        s1 += __shfl_xor_sync(0xffffffffu, s1, 1);
        s1 += __shfl_xor_sync(0xffffffffu, s1, 2);
        l0 = l0 * al0 + s0;
        l1 = l1 * al1 + s1;

#pragma unroll
        for (int j = 0; j < 8; j++) {
            of[j][0] *= al0; of[j][1] *= al0;
            of[j][2] *= al1; of[j][3] *= al1;
        }

        // ---- split P into bf16 A-fragments ----
        uint32_t ah[4][4], alf[4][4];
#pragma unroll
        for (int kk = 0; kk < 4; kk++) {
            float c00 = sf[2 * kk][0], c01 = sf[2 * kk][1];
            float c02 = sf[2 * kk][2], c03 = sf[2 * kk][3];
            float c10 = sf[2 * kk + 1][0], c11 = sf[2 * kk + 1][1];
            float c12 = sf[2 * kk + 1][2], c13 = sf[2 * kk + 1][3];
            uint32_t h0 = pack_bf16(c00, c01), h1 = pack_bf16(c02, c03);
            uint32_t h2 = pack_bf16(c10, c11), h3 = pack_bf16(c12, c13);
            ah[kk][0] = h0; ah[kk][1] = h1; ah[kk][2] = h2; ah[kk][3] = h3;
            __nv_bfloat162 b0 = *(__nv_bfloat162*)&h0;
            __nv_bfloat162 b1 = *(__nv_bfloat162*)&h1;
            __nv_bfloat162 b2 = *(__nv_bfloat162*)&h2;
            __nv_bfloat162 b3 = *(__nv_bfloat162*)&h3;
            alf[kk][0] = pack_bf16(c00 - __bfloat162float(b0.x), c01 - __bfloat162float(b0.y));
            alf[kk][1] = pack_bf16(c02 - __bfloat162float(b1.x), c03 - __bfloat162float(b1.y));
            alf[kk][2] = pack_bf16(c10 - __bfloat162float(b2.x), c11 - __bfloat162float(b2.y));
            alf[kk][3] = pack_bf16(c12 - __bfloat162float(b3.x), c13 - __bfloat162float(b3.y));
        }

        CP_WAIT(0);          // V tile fully landed
        __syncthreads();

        // ---- O += P' V': Phi*Vhi, Plo*Vhi, Phi*Vlo ----
#pragma unroll
        for (int ks12 = 0; ks12 < 12; ks12++) {
            int kk = ks12 & 3, sel = ks12 >> 2;
            uint32_t* A = (sel == 1) ? alf[kk] : ah[kk];
            int k0 = (sel == 2 ? 64 : 0) + kk * 16;
#pragma unroll
            for (int p = 0; p < 4; p++) {
                uint32_t b0, b1, b2, b3;
                ldsm4(b0, b1, b2, b3,
                      vsa + ((p * 16 + (li >> 1) * 8 + lr) * VPAD + k0 + (li & 1) * 8) * 2);
                mma16816(of[2 * p],     A[0], A[1], A[2], A[3], b0, b1);
                mma16816(of[2 * p + 1], A[0], A[1], A[2], A[3], b2, b3);
            }
        }
        __syncthreads();   // protect ks/vs before next tile's loads
    }

    // ---- epilogue: write split [hi|lo|hi] directly into aoc ----
    float inv0 = 1.f / l0, inv1 = 1.f / l1;
    int row0 = b * SEQ + qt * 64 + w * 16 + r0;
    int row1 = row0 + 8;
#pragma unroll
    for (int j = 0; j < 8; j++) {
        int colq = h * 64 + 8 * j + cc;
        {
            float v0 = of[j][0] * inv0, v1 = of[j][1] * inv0;
            uint32_t hp = pack_bf16(v0, v1);
            __nv_bfloat162 hb = *(__nv_bfloat162*)&hp;
            uint32_t lp = pack_bf16(v0 - __bfloat162float(hb.x), v1 - __bfloat162float(hb.y));
            uint32_t* base = (uint32_t*)(aoc + (size_t)row0 * GK + colq);
            base[0]              = hp;
            *(uint32_t*)((char*)base + 1024 * 2) = lp;
            *(uint32_t*)((char*)base + 2048 * 2) = hp;
        }
        {
            float v0 = of[j][2] * inv1, v1 = of[j][3] * inv1;
            uint32_t hp = pack_bf16(v0, v1);
            __nv_bfloat162 hb = *(__nv_bfloat162*)&hp;
            uint32_t lp = pack_bf16(v0 - __bfloat162float(hb.x), v1 - __bfloat162float(hb.y));
            uint32_t* base = (uint32_t*)(aoc + (size_t)row1 * GK + colq);
            base[0]              = hp;
            *(uint32_t*)((char*)base + 1024 * 2) = lp;
            *(uint32_t*)((char*)base + 2048 * 2) = hp;
        }
    }
}

// ---------------------------------------------------------------------------
extern "C" void kernel_launch(void* const* d_in, const int* in_sizes, int n_in,
                              void* d_out, int out_size) {
    const float* x    = (const float*)d_in[0];
    const float* cosT = (const float*)d_in[1];
    const float* sinT = (const float*)d_in[2];
    // d_in[3] = mask: unused
    const float* wq   = (const float*)d_in[4];
    const float* wk   = (const float*)d_in[5];
    const float* wv   = (const float*)d_in[6];
    const float* wo   = (const float*)d_in[7];

    float* out  = (float*)d_out;
    float* kout = out + OUT_ELEMS;
    float* vout = out + OUT_ELEMS + KV_ELEMS;

    float* qkv;
    __nv_bfloat16 *xc, *aoc, *wqkvt, *wot, *qb, *kb, *vhi, *vlo;
    cudaGetSymbolAddress((void**)&qkv, g_qkv);
    cudaGetSymbolAddress((void**)&xc,  g_xc);
    cudaGetSymbolAddress((void**)&aoc, g_aoc);
    cudaGetSymbolAddress((void**)&wqkvt, g_wqkvt);
    cudaGetSymbolAddress((void**)&wot, g_wot);
    cudaGetSymbolAddress((void**)&qb,  g_qb);
    cudaGetSymbolAddress((void**)&kb,  g_kb);
    cudaGetSymbolAddress((void**)&vhi, g_vhi);
    cudaGetSymbolAddress((void**)&vlo, g_vlo);

    cudaFuncSetAttribute(attn_mma, cudaFuncAttributeMaxDynamicSharedMemorySize, ATTN2_SMEM);
    cudaFuncSetAttribute(gemm_mma, cudaFuncAttributeMaxDynamicSharedMemorySize, GEMM_SMEM);

    // Split conversions
    conv_a<<<(MTOT * DMODEL / 4 + 255) / 256, 256>>>(x, xc);
    dim3 wb(32, 8);
    conv_qkv<<<dim3(NQKV / 32, DMODEL / 32), wb>>>(wq, wk, wv, wqkvt);
    conv_w<<<dim3(DMODEL / 32, DMODEL / 32), wb>>>(wo, wot, DMODEL);

    // Fused QKV projection
    gemm_mma<<<dim3(NQKV / 128, MTOT / 128), 256, GEMM_SMEM>>>(xc, wqkvt, qkv, NQKV);

    // RoPE + split + fp32 kv-cache outputs
    finish_q<<<(BATCH * SEQ * NH * 32 + 255) / 256, 256>>>(qkv, cosT, sinT, qb);
    finish_k<<<(BATCH * SEQ * NKV * 32 + 255) / 256, 256>>>(qkv, cosT, sinT, kout, kb);
    finish_v<<<dim3(SEQ / 32, HD / 32, BATCH * NKV), dim3(32, 8)>>>(qkv, vout, vhi, vlo);

    // Tensor-core flash attention
    attn_mma<<<dim3(SEQ / 64, NH, BATCH), 128, ATTN2_SMEM>>>(qb, kb, vhi, vlo, aoc);

    // Output projection
    gemm_mma<<<dim3(DMODEL / 128, MTOT / 128), 256, GEMM_SMEM>>>(aoc, wot, out, DMODEL);
}